// round 2
// baseline (speedup 1.0000x reference)
#include <cuda_runtime.h>
#include <math.h>

#define EMBED 1024
#define HEADS 16
#define DH 64
#define BATCH 2
#define LQ 2048
#define LK 2048
#define MROWS (BATCH * LQ)   // 4096

// ---------------- scratch (static device globals; no allocation) ----------------
__device__ float g_Q[(size_t)MROWS * EMBED];
__device__ float g_K[(size_t)BATCH * LK * EMBED];
__device__ float g_V[(size_t)BATCH * LK * EMBED];
__device__ float g_CTX[(size_t)MROWS * EMBED];

// ---------------- GEMM: C[M,N] = A[M,K] @ W[N,K]^T + bias[N] --------------------
__global__ __launch_bounds__(256) void gemm_nt_bias(
    const float* __restrict__ A, const float* __restrict__ W,
    const float* __restrict__ bias, float* __restrict__ C,
    int M, int N, int K)
{
    __shared__ float As[8][128];
    __shared__ float Bs[8][128];

    const int tid = threadIdx.x;
    const int bm = blockIdx.y * 128;
    const int bn = blockIdx.x * 128;

    // load mapping: 256 threads, each loads one float4 of A-tile and W-tile per k-step
    const int lr = tid >> 1;          // 0..127 (row within tile)
    const int lc = (tid & 1) << 2;    // 0 or 4 (k offset within 8)

    // compute mapping: 16x16 threads, 8x8 microtile each
    const int row8 = (tid >> 4) << 3;
    const int col8 = (tid & 15) << 3;

    const float* Aptr = A + (size_t)(bm + lr) * K + lc;
    const float* Wptr = W + (size_t)(bn + lr) * K + lc;

    float acc[8][8];
#pragma unroll
    for (int i = 0; i < 8; i++)
#pragma unroll
        for (int j = 0; j < 8; j++) acc[i][j] = 0.f;

    for (int k0 = 0; k0 < K; k0 += 8) {
        float4 a = *(const float4*)(Aptr + k0);
        float4 b = *(const float4*)(Wptr + k0);
        As[lc + 0][lr] = a.x; As[lc + 1][lr] = a.y;
        As[lc + 2][lr] = a.z; As[lc + 3][lr] = a.w;
        Bs[lc + 0][lr] = b.x; Bs[lc + 1][lr] = b.y;
        Bs[lc + 2][lr] = b.z; Bs[lc + 3][lr] = b.w;
        __syncthreads();

#pragma unroll
        for (int kk = 0; kk < 8; kk++) {
            float4 a0 = *(const float4*)&As[kk][row8];
            float4 a1 = *(const float4*)&As[kk][row8 + 4];
            float4 b0 = *(const float4*)&Bs[kk][col8];
            float4 b1 = *(const float4*)&Bs[kk][col8 + 4];
            float af[8] = {a0.x, a0.y, a0.z, a0.w, a1.x, a1.y, a1.z, a1.w};
            float bf[8] = {b0.x, b0.y, b0.z, b0.w, b1.x, b1.y, b1.z, b1.w};
#pragma unroll
            for (int i = 0; i < 8; i++)
#pragma unroll
                for (int j = 0; j < 8; j++)
                    acc[i][j] = fmaf(af[i], bf[j], acc[i][j]);
        }
        __syncthreads();
    }

    // epilogue with bias
    float bb[8];
#pragma unroll
    for (int j = 0; j < 8; j++) bb[j] = bias[bn + col8 + j];
#pragma unroll
    for (int i = 0; i < 8; i++) {
        float* crow = C + (size_t)(bm + row8 + i) * N + bn + col8;
        float4 v0 = make_float4(acc[i][0] + bb[0], acc[i][1] + bb[1],
                                acc[i][2] + bb[2], acc[i][3] + bb[3]);
        float4 v1 = make_float4(acc[i][4] + bb[4], acc[i][5] + bb[5],
                                acc[i][6] + bb[6], acc[i][7] + bb[7]);
        *(float4*)(crow) = v0;
        *(float4*)(crow + 4) = v1;
    }
}

// ---------------- Flash attention: one CTA per (b, h, 64-query tile) ------------
__global__ __launch_bounds__(256) void flash_attn(
    const float* __restrict__ Q, const float* __restrict__ K,
    const float* __restrict__ V, float* __restrict__ CTX)
{
    __shared__ float Qs[64][68];
    __shared__ float Ks[64][68];   // reused for V tile
    __shared__ float Ps[64][68];

    const int b  = blockIdx.z;
    const int h  = blockIdx.y;
    const int q0 = blockIdx.x * 64;
    const int tid = threadIdx.x;
    const int ty = tid >> 4;       // 0..15 -> owns query rows ty*4..+3
    const int tx = tid & 15;       // 0..15 -> owns key cols / dh cols tx*4..+3
    const float scale = 0.125f;    // 1/sqrt(64)

    // load Q tile (pre-scaled)
    for (int idx = tid; idx < 64 * 16; idx += 256) {
        int r = idx >> 4, c4 = (idx & 15) << 2;
        float4 v = *(const float4*)&Q[((size_t)(b * LQ + q0 + r)) * EMBED + h * DH + c4];
        Qs[r][c4 + 0] = v.x * scale; Qs[r][c4 + 1] = v.y * scale;
        Qs[r][c4 + 2] = v.z * scale; Qs[r][c4 + 3] = v.w * scale;
    }

    float Oacc[4][4];
    float mrow[4], lrow[4];
#pragma unroll
    for (int i = 0; i < 4; i++) {
        mrow[i] = -1e30f; lrow[i] = 0.f;
#pragma unroll
        for (int d = 0; d < 4; d++) Oacc[i][d] = 0.f;
    }
    __syncthreads();

    for (int k0 = 0; k0 < LK; k0 += 64) {
        // load K tile
        for (int idx = tid; idx < 64 * 16; idx += 256) {
            int r = idx >> 4, c4 = (idx & 15) << 2;
            float4 v = *(const float4*)&K[((size_t)(b * LK + k0 + r)) * EMBED + h * DH + c4];
            Ks[r][c4 + 0] = v.x; Ks[r][c4 + 1] = v.y;
            Ks[r][c4 + 2] = v.z; Ks[r][c4 + 3] = v.w;
        }
        __syncthreads();

        // S = (Q * scale) @ K^T   (4x4 per thread)
        float S[4][4];
#pragma unroll
        for (int i = 0; i < 4; i++)
#pragma unroll
            for (int j = 0; j < 4; j++) S[i][j] = 0.f;

#pragma unroll 4
        for (int d = 0; d < DH; d += 4) {
            float4 qf[4], kf[4];
#pragma unroll
            for (int ii = 0; ii < 4; ii++) qf[ii] = *(const float4*)&Qs[ty * 4 + ii][d];
#pragma unroll
            for (int jj = 0; jj < 4; jj++) kf[jj] = *(const float4*)&Ks[tx * 4 + jj][d];
#pragma unroll
            for (int ii = 0; ii < 4; ii++)
#pragma unroll
                for (int jj = 0; jj < 4; jj++) {
                    S[ii][jj] = fmaf(qf[ii].x, kf[jj].x, S[ii][jj]);
                    S[ii][jj] = fmaf(qf[ii].y, kf[jj].y, S[ii][jj]);
                    S[ii][jj] = fmaf(qf[ii].z, kf[jj].z, S[ii][jj]);
                    S[ii][jj] = fmaf(qf[ii].w, kf[jj].w, S[ii][jj]);
                }
        }

        // online softmax update (row reductions over the 16 tx lanes)
#pragma unroll
        for (int ii = 0; ii < 4; ii++) {
            float mm = fmaxf(fmaxf(S[ii][0], S[ii][1]), fmaxf(S[ii][2], S[ii][3]));
#pragma unroll
            for (int off = 8; off >= 1; off >>= 1)
                mm = fmaxf(mm, __shfl_xor_sync(0xffffffffu, mm, off, 16));
            float mn = fmaxf(mrow[ii], mm);
            float corr = __expf(mrow[ii] - mn);   // 0 on first tile
            mrow[ii] = mn;
            float ls = 0.f;
#pragma unroll
            for (int jj = 0; jj < 4; jj++) {
                S[ii][jj] = __expf(S[ii][jj] - mn);
                ls += S[ii][jj];
            }
#pragma unroll
            for (int off = 8; off >= 1; off >>= 1)
                ls += __shfl_xor_sync(0xffffffffu, ls, off, 16);
            lrow[ii] = lrow[ii] * corr + ls;
#pragma unroll
            for (int dd = 0; dd < 4; dd++) Oacc[ii][dd] *= corr;
            *(float4*)&Ps[ty * 4 + ii][tx * 4] =
                make_float4(S[ii][0], S[ii][1], S[ii][2], S[ii][3]);
        }
        __syncthreads();   // P in smem; everyone done reading Ks

        // load V tile into Ks buffer
        for (int idx = tid; idx < 64 * 16; idx += 256) {
            int r = idx >> 4, c4 = (idx & 15) << 2;
            float4 v = *(const float4*)&V[((size_t)(b * LK + k0 + r)) * EMBED + h * DH + c4];
            Ks[r][c4 + 0] = v.x; Ks[r][c4 + 1] = v.y;
            Ks[r][c4 + 2] = v.z; Ks[r][c4 + 3] = v.w;
        }
        __syncthreads();

        // O += P @ V
#pragma unroll 4
        for (int j = 0; j < 64; j += 4) {
            float4 pf[4], vf[4];
#pragma unroll
            for (int ii = 0; ii < 4; ii++) pf[ii] = *(const float4*)&Ps[ty * 4 + ii][j];
#pragma unroll
            for (int jt = 0; jt < 4; jt++) vf[jt] = *(const float4*)&Ks[j + jt][tx * 4];
#pragma unroll
            for (int ii = 0; ii < 4; ii++) {
                Oacc[ii][0] = fmaf(pf[ii].x, vf[0].x, Oacc[ii][0]);
                Oacc[ii][0] = fmaf(pf[ii].y, vf[1].x, Oacc[ii][0]);
                Oacc[ii][0] = fmaf(pf[ii].z, vf[2].x, Oacc[ii][0]);
                Oacc[ii][0] = fmaf(pf[ii].w, vf[3].x, Oacc[ii][0]);
                Oacc[ii][1] = fmaf(pf[ii].x, vf[0].y, Oacc[ii][1]);
                Oacc[ii][1] = fmaf(pf[ii].y, vf[1].y, Oacc[ii][1]);
                Oacc[ii][1] = fmaf(pf[ii].z, vf[2].y, Oacc[ii][1]);
                Oacc[ii][1] = fmaf(pf[ii].w, vf[3].y, Oacc[ii][1]);
                Oacc[ii][2] = fmaf(pf[ii].x, vf[0].z, Oacc[ii][2]);
                Oacc[ii][2] = fmaf(pf[ii].y, vf[1].z, Oacc[ii][2]);
                Oacc[ii][2] = fmaf(pf[ii].z, vf[2].z, Oacc[ii][2]);
                Oacc[ii][2] = fmaf(pf[ii].w, vf[3].z, Oacc[ii][2]);
                Oacc[ii][3] = fmaf(pf[ii].x, vf[0].w, Oacc[ii][3]);
                Oacc[ii][3] = fmaf(pf[ii].y, vf[1].w, Oacc[ii][3]);
                Oacc[ii][3] = fmaf(pf[ii].z, vf[2].w, Oacc[ii][3]);
                Oacc[ii][3] = fmaf(pf[ii].w, vf[3].w, Oacc[ii][3]);
            }
        }
        __syncthreads();   // before next K-tile overwrites Ks
    }

    // normalize and write ctx (layout [B, L, H*Dh] identical to Q layout)
#pragma unroll
    for (int ii = 0; ii < 4; ii++) {
        float inv = 1.0f / lrow[ii];
        size_t row = (size_t)(b * LQ + q0 + ty * 4 + ii);
        *(float4*)&CTX[row * EMBED + h * DH + tx * 4] =
            make_float4(Oacc[ii][0] * inv, Oacc[ii][1] * inv,
                        Oacc[ii][2] * inv, Oacc[ii][3] * inv);
    }
}

// ---------------- residual + LayerNorm (in-place on out) ------------------------
__global__ __launch_bounds__(256) void resid_ln(
    float* __restrict__ out, const float* __restrict__ qseq,
    const float* __restrict__ gamma, const float* __restrict__ beta)
{
    const int row = blockIdx.x;
    const int tid = threadIdx.x;
    const size_t base = (size_t)row * EMBED + tid * 4;

    float4 o = *(float4*)&out[base];
    float4 q = *(const float4*)&qseq[base];
    float x0 = o.x + q.x, x1 = o.y + q.y, x2 = o.z + q.z, x3 = o.w + q.w;

    float s  = x0 + x1 + x2 + x3;
    float ss = fmaf(x0, x0, fmaf(x1, x1, fmaf(x2, x2, x3 * x3)));
#pragma unroll
    for (int off = 16; off >= 1; off >>= 1) {
        s  += __shfl_xor_sync(0xffffffffu, s, off);
        ss += __shfl_xor_sync(0xffffffffu, ss, off);
    }

    __shared__ float rs[8], rss[8];
    const int warp = tid >> 5, lane = tid & 31;
    if (lane == 0) { rs[warp] = s; rss[warp] = ss; }
    __syncthreads();
    if (tid == 0) {
        float S = 0.f, SS = 0.f;
#pragma unroll
        for (int w = 0; w < 8; w++) { S += rs[w]; SS += rss[w]; }
        rs[0] = S; rss[0] = SS;
    }
    __syncthreads();

    const float mean = rs[0] * (1.0f / EMBED);
    const float var  = rss[0] * (1.0f / EMBED) - mean * mean;
    const float r    = rsqrtf(var + 1e-5f);

    float4 g = *(const float4*)&gamma[tid * 4];
    float4 bt = *(const float4*)&beta[tid * 4];
    float4 y = make_float4((x0 - mean) * r * g.x + bt.x,
                           (x1 - mean) * r * g.y + bt.y,
                           (x2 - mean) * r * g.z + bt.z,
                           (x3 - mean) * r * g.w + bt.w);
    *(float4*)&out[base] = y;
}

// ---------------- launch ---------------------------------------------------------
extern "C" void kernel_launch(void* const* d_in, const int* in_sizes, int n_in,
                              void* d_out, int out_size)
{
    const float* qseq  = (const float*)d_in[0];
    const float* kvseq = (const float*)d_in[1];
    // d_in[2] = prompt_size (unused: reference applies no masking)
    const float* Wq = (const float*)d_in[3];
    const float* bq = (const float*)d_in[4];
    const float* Wk = (const float*)d_in[5];
    const float* bk = (const float*)d_in[6];
    const float* Wv = (const float*)d_in[7];
    const float* bv = (const float*)d_in[8];
    const float* Wo = (const float*)d_in[9];
    const float* bo = (const float*)d_in[10];
    const float* gamma = (const float*)d_in[11];
    const float* beta  = (const float*)d_in[12];
    float* out = (float*)d_out;

    float *gQ, *gK, *gV, *gC;
    cudaGetSymbolAddress((void**)&gQ, g_Q);
    cudaGetSymbolAddress((void**)&gK, g_K);
    cudaGetSymbolAddress((void**)&gV, g_V);
    cudaGetSymbolAddress((void**)&gC, g_CTX);

    dim3 ggrid(EMBED / 128, MROWS / 128);   // (8, 32)
    gemm_nt_bias<<<ggrid, 256>>>(qseq,  Wq, bq, gQ, MROWS, EMBED, EMBED);
    gemm_nt_bias<<<ggrid, 256>>>(kvseq, Wk, bk, gK, MROWS, EMBED, EMBED);
    gemm_nt_bias<<<ggrid, 256>>>(kvseq, Wv, bv, gV, MROWS, EMBED, EMBED);

    dim3 agrid(LQ / 64, HEADS, BATCH);      // (32, 16, 2)
    flash_attn<<<agrid, 256>>>(gQ, gK, gV, gC);

    gemm_nt_bias<<<ggrid, 256>>>(gC, Wo, bo, out, MROWS, EMBED, EMBED);

    resid_ln<<<MROWS, 256>>>(out, qseq, gamma, beta);
}

// round 4
// speedup vs baseline: 1.2994x; 1.2994x over previous
#include <cuda_runtime.h>
#include <cuda_bf16.h>
#include <cstdint>
#include <math.h>

#define EMBED 1024
#define HEADS 16
#define DH 64
#define BATCH 2
#define LQ 2048
#define LK 2048
#define MROWS (BATCH * LQ)   // 4096

// ---------------- scratch (static device globals; no allocation) ----------------
__device__ float g_Q[(size_t)MROWS * EMBED];
__device__ float g_K[(size_t)BATCH * LK * EMBED];
__device__ float g_V[(size_t)BATCH * LK * EMBED];
__device__ float g_CTX[(size_t)MROWS * EMBED];

// bf16 split operands
__device__ __nv_bfloat16 g_Aq_hi[(size_t)MROWS * EMBED];
__device__ __nv_bfloat16 g_Aq_lo[(size_t)MROWS * EMBED];
__device__ __nv_bfloat16 g_Akv_hi[(size_t)MROWS * EMBED];
__device__ __nv_bfloat16 g_Akv_lo[(size_t)MROWS * EMBED];
__device__ __nv_bfloat16 g_Actx_hi[(size_t)MROWS * EMBED];
__device__ __nv_bfloat16 g_Actx_lo[(size_t)MROWS * EMBED];
__device__ __nv_bfloat16 g_Wq_hi[(size_t)EMBED * EMBED];
__device__ __nv_bfloat16 g_Wq_lo[(size_t)EMBED * EMBED];
__device__ __nv_bfloat16 g_Wk_hi[(size_t)EMBED * EMBED];
__device__ __nv_bfloat16 g_Wk_lo[(size_t)EMBED * EMBED];
__device__ __nv_bfloat16 g_Wv_hi[(size_t)EMBED * EMBED];
__device__ __nv_bfloat16 g_Wv_lo[(size_t)EMBED * EMBED];
__device__ __nv_bfloat16 g_Wo_hi[(size_t)EMBED * EMBED];
__device__ __nv_bfloat16 g_Wo_lo[(size_t)EMBED * EMBED];

// ---------------- PTX helpers (sm_80+ baseline features only) --------------------
__device__ __forceinline__ uint32_t smem_u32(const void* p) {
    uint32_t a;
    asm("{ .reg .u64 t; cvta.to.shared.u64 t, %1; cvt.u32.u64 %0, t; }" : "=r"(a) : "l"(p));
    return a;
}

#define LDSM4(r, addr) \
    asm volatile("ldmatrix.sync.aligned.m8n8.x4.shared.b16 {%0,%1,%2,%3}, [%4];" \
                 : "=r"((r)[0]), "=r"((r)[1]), "=r"((r)[2]), "=r"((r)[3]) : "r"(addr))

#define MMA16816(d, a, b0, b1) \
    asm volatile("mma.sync.aligned.m16n8k16.row.col.f32.bf16.bf16.f32 " \
                 "{%0,%1,%2,%3}, {%4,%5,%6,%7}, {%8,%9}, {%0,%1,%2,%3};" \
                 : "+f"((d)[0]), "+f"((d)[1]), "+f"((d)[2]), "+f"((d)[3]) \
                 : "r"((a)[0]), "r"((a)[1]), "r"((a)[2]), "r"((a)[3]), "r"(b0), "r"(b1))

// ---------------- fp32 -> bf16 (hi, lo) split ------------------------------------
__global__ __launch_bounds__(256) void split_bf16(
    const float* __restrict__ x, __nv_bfloat16* __restrict__ hi,
    __nv_bfloat16* __restrict__ lo, int n4)
{
    int i = blockIdx.x * 256 + threadIdx.x;
    if (i >= n4) return;
    float4 v = *(const float4*)(x + (size_t)i * 4);
    __nv_bfloat16 h0 = __float2bfloat16_rn(v.x);
    __nv_bfloat16 h1 = __float2bfloat16_rn(v.y);
    __nv_bfloat16 h2 = __float2bfloat16_rn(v.z);
    __nv_bfloat16 h3 = __float2bfloat16_rn(v.w);
    __nv_bfloat16 l0 = __float2bfloat16_rn(v.x - __bfloat162float(h0));
    __nv_bfloat16 l1 = __float2bfloat16_rn(v.y - __bfloat162float(h1));
    __nv_bfloat16 l2 = __float2bfloat16_rn(v.z - __bfloat162float(h2));
    __nv_bfloat16 l3 = __float2bfloat16_rn(v.w - __bfloat162float(h3));
    __nv_bfloat162 hh0; hh0.x = h0; hh0.y = h1;
    __nv_bfloat162 hh1; hh1.x = h2; hh1.y = h3;
    __nv_bfloat162 ll0; ll0.x = l0; ll0.y = l1;
    __nv_bfloat162 ll1; ll1.x = l2; ll1.y = l3;
    *(__nv_bfloat162*)(hi + (size_t)i * 4)     = hh0;
    *(__nv_bfloat162*)(hi + (size_t)i * 4 + 2) = hh1;
    *(__nv_bfloat162*)(lo + (size_t)i * 4)     = ll0;
    *(__nv_bfloat162*)(lo + (size_t)i * 4 + 2) = ll1;
}

// ---------------- HMMA GEMM: C[4096,1024] = A @ W^T + bias ----------------------
// split precision: C = Ah*Bh + Ah*Bl + Al*Bh
// CTA tile 128x128, 8 warps of 64x32, BK=32, smem row stride 40 bf16 (80B).
#define SSTR 40

__global__ __launch_bounds__(256, 1) void gemm_hmma(
    const __nv_bfloat16* __restrict__ Ah, const __nv_bfloat16* __restrict__ Al,
    const __nv_bfloat16* __restrict__ Bh, const __nv_bfloat16* __restrict__ Bl,
    const float* __restrict__ bias, float* __restrict__ C)
{
    __shared__ __align__(16) __nv_bfloat16 sAh[128 * SSTR];
    __shared__ __align__(16) __nv_bfloat16 sAl[128 * SSTR];
    __shared__ __align__(16) __nv_bfloat16 sBh[128 * SSTR];
    __shared__ __align__(16) __nv_bfloat16 sBl[128 * SSTR];

    const int tid  = threadIdx.x;
    const int wid  = tid >> 5;
    const int lane = tid & 31;
    const int bm = blockIdx.y * 128;
    const int bn = blockIdx.x * 128;
    const int wm = (wid >> 2) * 64;   // warp row offset in CTA tile
    const int wn = (wid & 3) * 32;    // warp col offset in CTA tile

    // global-load mapping: chunk c = tid + t*256 (t=0,1); row = c>>2, koff = (c&3)*8
    const int r0g = tid >> 2;              // t=0 row
    const int r1g = (tid + 256) >> 2;      // t=1 row
    const int k0g = (tid & 3) * 8;         // same koff both chunks

    float4 pAh[2], pAl[2], pBh[2], pBl[2];

    // ldmatrix per-lane offsets
    const int a_row = (lane & 7) + ((lane >> 3) & 1) * 8;
    const int a_kof = (lane >> 4) * 8;
    const int b_row = (lane & 7) + (lane >> 4) * 8;
    const int b_kof = ((lane >> 3) & 1) * 8;

    const uint32_t uAh = smem_u32(sAh), uAl = smem_u32(sAl);
    const uint32_t uBh = smem_u32(sBh), uBl = smem_u32(sBl);

    float acc[4][4][4];
#pragma unroll
    for (int i = 0; i < 4; i++)
#pragma unroll
        for (int j = 0; j < 4; j++)
#pragma unroll
            for (int v = 0; v < 4; v++) acc[i][j][v] = 0.f;

    // prefetch kb=0
    {
        size_t a0 = (size_t)(bm + r0g) * EMBED + k0g;
        size_t a1 = (size_t)(bm + r1g) * EMBED + k0g;
        size_t b0 = (size_t)(bn + r0g) * EMBED + k0g;
        size_t b1 = (size_t)(bn + r1g) * EMBED + k0g;
        pAh[0] = *(const float4*)(Ah + a0); pAh[1] = *(const float4*)(Ah + a1);
        pAl[0] = *(const float4*)(Al + a0); pAl[1] = *(const float4*)(Al + a1);
        pBh[0] = *(const float4*)(Bh + b0); pBh[1] = *(const float4*)(Bh + b1);
        pBl[0] = *(const float4*)(Bl + b0); pBl[1] = *(const float4*)(Bl + b1);
    }

    for (int kb = 0; kb < 32; kb++) {
        // store staged tiles
        *(float4*)&sAh[r0g * SSTR + k0g] = pAh[0];
        *(float4*)&sAh[r1g * SSTR + k0g] = pAh[1];
        *(float4*)&sAl[r0g * SSTR + k0g] = pAl[0];
        *(float4*)&sAl[r1g * SSTR + k0g] = pAl[1];
        *(float4*)&sBh[r0g * SSTR + k0g] = pBh[0];
        *(float4*)&sBh[r1g * SSTR + k0g] = pBh[1];
        *(float4*)&sBl[r0g * SSTR + k0g] = pBl[0];
        *(float4*)&sBl[r1g * SSTR + k0g] = pBl[1];
        __syncthreads();

        if (kb < 31) {
            const int kn = (kb + 1) * 32;
            size_t a0 = (size_t)(bm + r0g) * EMBED + kn + k0g;
            size_t a1 = (size_t)(bm + r1g) * EMBED + kn + k0g;
            size_t b0 = (size_t)(bn + r0g) * EMBED + kn + k0g;
            size_t b1 = (size_t)(bn + r1g) * EMBED + kn + k0g;
            pAh[0] = *(const float4*)(Ah + a0); pAh[1] = *(const float4*)(Ah + a1);
            pAl[0] = *(const float4*)(Al + a0); pAl[1] = *(const float4*)(Al + a1);
            pBh[0] = *(const float4*)(Bh + b0); pBh[1] = *(const float4*)(Bh + b1);
            pBl[0] = *(const float4*)(Bl + b0); pBl[1] = *(const float4*)(Bl + b1);
        }

#pragma unroll
        for (int ks = 0; ks < 2; ks++) {
            const int k0 = ks * 16;
            uint32_t fAh[4][4], fAl[4][4], fBh[2][4], fBl[2][4];
#pragma unroll
            for (int mt = 0; mt < 4; mt++) {
                uint32_t off = (uint32_t)((wm + mt * 16 + a_row) * SSTR + k0 + a_kof) * 2;
                LDSM4(fAh[mt], uAh + off);
                LDSM4(fAl[mt], uAl + off);
            }
#pragma unroll
            for (int np = 0; np < 2; np++) {
                uint32_t off = (uint32_t)((wn + np * 16 + b_row) * SSTR + k0 + b_kof) * 2;
                LDSM4(fBh[np], uBh + off);
                LDSM4(fBl[np], uBl + off);
            }
#pragma unroll
            for (int mt = 0; mt < 4; mt++) {
#pragma unroll
                for (int nt = 0; nt < 4; nt++) {
                    const int np = nt >> 1, pr = (nt & 1) * 2;
                    MMA16816(acc[mt][nt], fAh[mt], fBh[np][pr], fBh[np][pr + 1]);
                    MMA16816(acc[mt][nt], fAh[mt], fBl[np][pr], fBl[np][pr + 1]);
                    MMA16816(acc[mt][nt], fAl[mt], fBh[np][pr], fBh[np][pr + 1]);
                }
            }
        }
        __syncthreads();
    }

    // epilogue with bias
    const int er = lane >> 2;
    const int ec = (lane & 3) * 2;
#pragma unroll
    for (int nt = 0; nt < 4; nt++) {
        const int gc = bn + wn + nt * 8 + ec;
        const float bx = bias[gc], by = bias[gc + 1];
#pragma unroll
        for (int mt = 0; mt < 4; mt++) {
            const int gr = bm + wm + mt * 16 + er;
            float2 v0 = make_float2(acc[mt][nt][0] + bx, acc[mt][nt][1] + by);
            float2 v1 = make_float2(acc[mt][nt][2] + bx, acc[mt][nt][3] + by);
            *(float2*)&C[(size_t)gr * EMBED + gc] = v0;
            *(float2*)&C[(size_t)(gr + 8) * EMBED + gc] = v1;
        }
    }
}

// ---------------- Flash attention: one CTA per (b, h, 64-query tile) ------------
__global__ __launch_bounds__(256) void flash_attn(
    const float* __restrict__ Q, const float* __restrict__ K,
    const float* __restrict__ V, float* __restrict__ CTX)
{
    __shared__ float Qs[64][68];
    __shared__ float Ks[64][68];   // reused for V tile
    __shared__ float Ps[64][68];

    const int b  = blockIdx.z;
    const int h  = blockIdx.y;
    const int q0 = blockIdx.x * 64;
    const int tid = threadIdx.x;
    const int ty = tid >> 4;
    const int tx = tid & 15;
    const float scale = 0.125f;    // 1/sqrt(64)

    for (int idx = tid; idx < 64 * 16; idx += 256) {
        int r = idx >> 4, c4 = (idx & 15) << 2;
        float4 v = *(const float4*)&Q[((size_t)(b * LQ + q0 + r)) * EMBED + h * DH + c4];
        Qs[r][c4 + 0] = v.x * scale; Qs[r][c4 + 1] = v.y * scale;
        Qs[r][c4 + 2] = v.z * scale; Qs[r][c4 + 3] = v.w * scale;
    }

    float Oacc[4][4];
    float mrow[4], lrow[4];
#pragma unroll
    for (int i = 0; i < 4; i++) {
        mrow[i] = -1e30f; lrow[i] = 0.f;
#pragma unroll
        for (int d = 0; d < 4; d++) Oacc[i][d] = 0.f;
    }
    __syncthreads();

    for (int k0 = 0; k0 < LK; k0 += 64) {
        for (int idx = tid; idx < 64 * 16; idx += 256) {
            int r = idx >> 4, c4 = (idx & 15) << 2;
            float4 v = *(const float4*)&K[((size_t)(b * LK + k0 + r)) * EMBED + h * DH + c4];
            Ks[r][c4 + 0] = v.x; Ks[r][c4 + 1] = v.y;
            Ks[r][c4 + 2] = v.z; Ks[r][c4 + 3] = v.w;
        }
        __syncthreads();

        float S[4][4];
#pragma unroll
        for (int i = 0; i < 4; i++)
#pragma unroll
            for (int j = 0; j < 4; j++) S[i][j] = 0.f;

#pragma unroll 4
        for (int d = 0; d < DH; d += 4) {
            float4 qf[4], kf[4];
#pragma unroll
            for (int ii = 0; ii < 4; ii++) qf[ii] = *(const float4*)&Qs[ty * 4 + ii][d];
#pragma unroll
            for (int jj = 0; jj < 4; jj++) kf[jj] = *(const float4*)&Ks[tx * 4 + jj][d];
#pragma unroll
            for (int ii = 0; ii < 4; ii++)
#pragma unroll
                for (int jj = 0; jj < 4; jj++) {
                    S[ii][jj] = fmaf(qf[ii].x, kf[jj].x, S[ii][jj]);
                    S[ii][jj] = fmaf(qf[ii].y, kf[jj].y, S[ii][jj]);
                    S[ii][jj] = fmaf(qf[ii].z, kf[jj].z, S[ii][jj]);
                    S[ii][jj] = fmaf(qf[ii].w, kf[jj].w, S[ii][jj]);
                }
        }

#pragma unroll
        for (int ii = 0; ii < 4; ii++) {
            float mm = fmaxf(fmaxf(S[ii][0], S[ii][1]), fmaxf(S[ii][2], S[ii][3]));
#pragma unroll
            for (int off = 8; off >= 1; off >>= 1)
                mm = fmaxf(mm, __shfl_xor_sync(0xffffffffu, mm, off, 16));
            float mn = fmaxf(mrow[ii], mm);
            float corr = __expf(mrow[ii] - mn);
            mrow[ii] = mn;
            float ls = 0.f;
#pragma unroll
            for (int jj = 0; jj < 4; jj++) {
                S[ii][jj] = __expf(S[ii][jj] - mn);
                ls += S[ii][jj];
            }
#pragma unroll
            for (int off = 8; off >= 1; off >>= 1)
                ls += __shfl_xor_sync(0xffffffffu, ls, off, 16);
            lrow[ii] = lrow[ii] * corr + ls;
#pragma unroll
            for (int dd = 0; dd < 4; dd++) Oacc[ii][dd] *= corr;
            *(float4*)&Ps[ty * 4 + ii][tx * 4] =
                make_float4(S[ii][0], S[ii][1], S[ii][2], S[ii][3]);
        }
        __syncthreads();

        for (int idx = tid; idx < 64 * 16; idx += 256) {
            int r = idx >> 4, c4 = (idx & 15) << 2;
            float4 v = *(const float4*)&V[((size_t)(b * LK + k0 + r)) * EMBED + h * DH + c4];
            Ks[r][c4 + 0] = v.x; Ks[r][c4 + 1] = v.y;
            Ks[r][c4 + 2] = v.z; Ks[r][c4 + 3] = v.w;
        }
        __syncthreads();

#pragma unroll 4
        for (int j = 0; j < 64; j += 4) {
            float4 pf[4], vf[4];
#pragma unroll
            for (int ii = 0; ii < 4; ii++) pf[ii] = *(const float4*)&Ps[ty * 4 + ii][j];
#pragma unroll
            for (int jt = 0; jt < 4; jt++) vf[jt] = *(const float4*)&Ks[j + jt][tx * 4];
#pragma unroll
            for (int ii = 0; ii < 4; ii++) {
                Oacc[ii][0] = fmaf(pf[ii].x, vf[0].x, Oacc[ii][0]);
                Oacc[ii][0] = fmaf(pf[ii].y, vf[1].x, Oacc[ii][0]);
                Oacc[ii][0] = fmaf(pf[ii].z, vf[2].x, Oacc[ii][0]);
                Oacc[ii][0] = fmaf(pf[ii].w, vf[3].x, Oacc[ii][0]);
                Oacc[ii][1] = fmaf(pf[ii].x, vf[0].y, Oacc[ii][1]);
                Oacc[ii][1] = fmaf(pf[ii].y, vf[1].y, Oacc[ii][1]);
                Oacc[ii][1] = fmaf(pf[ii].z, vf[2].y, Oacc[ii][1]);
                Oacc[ii][1] = fmaf(pf[ii].w, vf[3].y, Oacc[ii][1]);
                Oacc[ii][2] = fmaf(pf[ii].x, vf[0].z, Oacc[ii][2]);
                Oacc[ii][2] = fmaf(pf[ii].y, vf[1].z, Oacc[ii][2]);
                Oacc[ii][2] = fmaf(pf[ii].z, vf[2].z, Oacc[ii][2]);
                Oacc[ii][2] = fmaf(pf[ii].w, vf[3].z, Oacc[ii][2]);
                Oacc[ii][3] = fmaf(pf[ii].x, vf[0].w, Oacc[ii][3]);
                Oacc[ii][3] = fmaf(pf[ii].y, vf[1].w, Oacc[ii][3]);
                Oacc[ii][3] = fmaf(pf[ii].z, vf[2].w, Oacc[ii][3]);
                Oacc[ii][3] = fmaf(pf[ii].w, vf[3].w, Oacc[ii][3]);
            }
        }
        __syncthreads();
    }

#pragma unroll
    for (int ii = 0; ii < 4; ii++) {
        float inv = 1.0f / lrow[ii];
        size_t row = (size_t)(b * LQ + q0 + ty * 4 + ii);
        *(float4*)&CTX[row * EMBED + h * DH + tx * 4] =
            make_float4(Oacc[ii][0] * inv, Oacc[ii][1] * inv,
                        Oacc[ii][2] * inv, Oacc[ii][3] * inv);
    }
}

// ---------------- residual + LayerNorm (in-place on out) ------------------------
__global__ __launch_bounds__(256) void resid_ln(
    float* __restrict__ out, const float* __restrict__ qseq,
    const float* __restrict__ gamma, const float* __restrict__ beta)
{
    const int row = blockIdx.x;
    const int tid = threadIdx.x;
    const size_t base = (size_t)row * EMBED + tid * 4;

    float4 o = *(float4*)&out[base];
    float4 q = *(const float4*)&qseq[base];
    float x0 = o.x + q.x, x1 = o.y + q.y, x2 = o.z + q.z, x3 = o.w + q.w;

    float s  = x0 + x1 + x2 + x3;
    float ss = fmaf(x0, x0, fmaf(x1, x1, fmaf(x2, x2, x3 * x3)));
#pragma unroll
    for (int off = 16; off >= 1; off >>= 1) {
        s  += __shfl_xor_sync(0xffffffffu, s, off);
        ss += __shfl_xor_sync(0xffffffffu, ss, off);
    }

    __shared__ float rs[8], rss[8];
    const int warp = tid >> 5, lane = tid & 31;
    if (lane == 0) { rs[warp] = s; rss[warp] = ss; }
    __syncthreads();
    if (tid == 0) {
        float S = 0.f, SS = 0.f;
#pragma unroll
        for (int w = 0; w < 8; w++) { S += rs[w]; SS += rss[w]; }
        rs[0] = S; rss[0] = SS;
    }
    __syncthreads();

    const float mean = rs[0] * (1.0f / EMBED);
    const float var  = rss[0] * (1.0f / EMBED) - mean * mean;
    const float r    = rsqrtf(var + 1e-5f);

    float4 g = *(const float4*)&gamma[tid * 4];
    float4 bt = *(const float4*)&beta[tid * 4];
    float4 y = make_float4((x0 - mean) * r * g.x + bt.x,
                           (x1 - mean) * r * g.y + bt.y,
                           (x2 - mean) * r * g.z + bt.z,
                           (x3 - mean) * r * g.w + bt.w);
    *(float4*)&out[base] = y;
}

// ---------------- launch ---------------------------------------------------------
extern "C" void kernel_launch(void* const* d_in, const int* in_sizes, int n_in,
                              void* d_out, int out_size)
{
    const float* qseq  = (const float*)d_in[0];
    const float* kvseq = (const float*)d_in[1];
    // d_in[2] = prompt_size (unused: reference applies no masking)
    const float* Wq = (const float*)d_in[3];
    const float* bq = (const float*)d_in[4];
    const float* Wk = (const float*)d_in[5];
    const float* bk = (const float*)d_in[6];
    const float* Wv = (const float*)d_in[7];
    const float* bv = (const float*)d_in[8];
    const float* Wo = (const float*)d_in[9];
    const float* bo = (const float*)d_in[10];
    const float* gamma = (const float*)d_in[11];
    const float* beta  = (const float*)d_in[12];
    float* out = (float*)d_out;

    float *gQ, *gK, *gV, *gC;
    cudaGetSymbolAddress((void**)&gQ, g_Q);
    cudaGetSymbolAddress((void**)&gK, g_K);
    cudaGetSymbolAddress((void**)&gV, g_V);
    cudaGetSymbolAddress((void**)&gC, g_CTX);

    __nv_bfloat16 *aqh, *aql, *akh, *akl, *ach, *acl;
    __nv_bfloat16 *wqh, *wql, *wkh, *wkl, *wvh, *wvl, *woh, *wol;
    cudaGetSymbolAddress((void**)&aqh, g_Aq_hi);  cudaGetSymbolAddress((void**)&aql, g_Aq_lo);
    cudaGetSymbolAddress((void**)&akh, g_Akv_hi); cudaGetSymbolAddress((void**)&akl, g_Akv_lo);
    cudaGetSymbolAddress((void**)&ach, g_Actx_hi);cudaGetSymbolAddress((void**)&acl, g_Actx_lo);
    cudaGetSymbolAddress((void**)&wqh, g_Wq_hi);  cudaGetSymbolAddress((void**)&wql, g_Wq_lo);
    cudaGetSymbolAddress((void**)&wkh, g_Wk_hi);  cudaGetSymbolAddress((void**)&wkl, g_Wk_lo);
    cudaGetSymbolAddress((void**)&wvh, g_Wv_hi);  cudaGetSymbolAddress((void**)&wvl, g_Wv_lo);
    cudaGetSymbolAddress((void**)&woh, g_Wo_hi);  cudaGetSymbolAddress((void**)&wol, g_Wo_lo);

    const int nA4 = MROWS * EMBED / 4;     // 1048576
    const int nW4 = EMBED * EMBED / 4;     // 262144

    split_bf16<<<(nA4 + 255) / 256, 256>>>(qseq,  aqh, aql, nA4);
    split_bf16<<<(nA4 + 255) / 256, 256>>>(kvseq, akh, akl, nA4);
    split_bf16<<<(nW4 + 255) / 256, 256>>>(Wq, wqh, wql, nW4);
    split_bf16<<<(nW4 + 255) / 256, 256>>>(Wk, wkh, wkl, nW4);
    split_bf16<<<(nW4 + 255) / 256, 256>>>(Wv, wvh, wvl, nW4);
    split_bf16<<<(nW4 + 255) / 256, 256>>>(Wo, woh, wol, nW4);

    dim3 ggrid(EMBED / 128, MROWS / 128);   // (8, 32)
    gemm_hmma<<<ggrid, 256>>>(aqh, aql, wqh, wql, bq, gQ);
    gemm_hmma<<<ggrid, 256>>>(akh, akl, wkh, wkl, bk, gK);
    gemm_hmma<<<ggrid, 256>>>(akh, akl, wvh, wvl, bv, gV);

    dim3 agrid(LQ / 64, HEADS, BATCH);      // (32, 16, 2)
    flash_attn<<<agrid, 256>>>(gQ, gK, gV, gC);

    split_bf16<<<(nA4 + 255) / 256, 256>>>(gC, ach, acl, nA4);
    gemm_hmma<<<ggrid, 256>>>(ach, acl, woh, wol, bo, out);

    resid_ln<<<MROWS, 256>>>(out, qseq, gamma, beta);
}

// round 7
// speedup vs baseline: 3.7880x; 2.9151x over previous
#include <cuda_runtime.h>
#include <cuda_bf16.h>
#include <cuda_fp16.h>
#include <cstdint>
#include <math.h>

#define EMBED 1024
#define HEADS 16
#define DH 64
#define BATCH 2
#define LQ 2048
#define LK 2048
#define MROWS (BATCH * LQ)   // 4096

// ---------------- scratch (static device globals; no allocation) ----------------
__device__ __half g_Qh[(size_t)MROWS * EMBED];
__device__ __half g_Kh[(size_t)MROWS * EMBED];
__device__ __half g_Vh[(size_t)MROWS * EMBED];

// bf16 split operands
__device__ __nv_bfloat16 g_Aq_hi[(size_t)MROWS * EMBED];
__device__ __nv_bfloat16 g_Aq_lo[(size_t)MROWS * EMBED];
__device__ __nv_bfloat16 g_Akv_hi[(size_t)MROWS * EMBED];
__device__ __nv_bfloat16 g_Akv_lo[(size_t)MROWS * EMBED];
__device__ __nv_bfloat16 g_Actx_hi[(size_t)MROWS * EMBED];
__device__ __nv_bfloat16 g_Actx_lo[(size_t)MROWS * EMBED];
__device__ __nv_bfloat16 g_Wq_hi[(size_t)EMBED * EMBED];
__device__ __nv_bfloat16 g_Wq_lo[(size_t)EMBED * EMBED];
__device__ __nv_bfloat16 g_Wk_hi[(size_t)EMBED * EMBED];
__device__ __nv_bfloat16 g_Wk_lo[(size_t)EMBED * EMBED];
__device__ __nv_bfloat16 g_Wv_hi[(size_t)EMBED * EMBED];
__device__ __nv_bfloat16 g_Wv_lo[(size_t)EMBED * EMBED];
__device__ __nv_bfloat16 g_Wo_hi[(size_t)EMBED * EMBED];
__device__ __nv_bfloat16 g_Wo_lo[(size_t)EMBED * EMBED];

// ---------------- PTX helpers (sm_80+ baseline features only) --------------------
__device__ __forceinline__ uint32_t smem_u32(const void* p) {
    uint32_t a;
    asm("{ .reg .u64 t; cvta.to.shared.u64 t, %1; cvt.u32.u64 %0, t; }" : "=r"(a) : "l"(p));
    return a;
}

#define LDSM4(r, addr) \
    asm volatile("ldmatrix.sync.aligned.m8n8.x4.shared.b16 {%0,%1,%2,%3}, [%4];" \
                 : "=r"((r)[0]), "=r"((r)[1]), "=r"((r)[2]), "=r"((r)[3]) : "r"(addr))

#define LDSM4T(r, addr) \
    asm volatile("ldmatrix.sync.aligned.m8n8.x4.trans.shared.b16 {%0,%1,%2,%3}, [%4];" \
                 : "=r"((r)[0]), "=r"((r)[1]), "=r"((r)[2]), "=r"((r)[3]) : "r"(addr))

#define MMA16816(d, a, b0, b1) \
    asm volatile("mma.sync.aligned.m16n8k16.row.col.f32.bf16.bf16.f32 " \
                 "{%0,%1,%2,%3}, {%4,%5,%6,%7}, {%8,%9}, {%0,%1,%2,%3};" \
                 : "+f"((d)[0]), "+f"((d)[1]), "+f"((d)[2]), "+f"((d)[3]) \
                 : "r"((a)[0]), "r"((a)[1]), "r"((a)[2]), "r"((a)[3]), "r"(b0), "r"(b1))

#define MMAF16(d, a, b0, b1) \
    asm volatile("mma.sync.aligned.m16n8k16.row.col.f32.f16.f16.f32 " \
                 "{%0,%1,%2,%3}, {%4,%5,%6,%7}, {%8,%9}, {%0,%1,%2,%3};" \
                 : "+f"((d)[0]), "+f"((d)[1]), "+f"((d)[2]), "+f"((d)[3]) \
                 : "r"((a)[0]), "r"((a)[1]), "r"((a)[2]), "r"((a)[3]), "r"(b0), "r"(b1))

__device__ __forceinline__ uint32_t pack_half2(float a, float b) {
    __half2 h = __floats2half2_rn(a, b);
    return *(uint32_t*)&h;
}

// exp(x) for x <= 0 on the fma/alu pipes (no MUFU). rel err ~2e-6.
__device__ __forceinline__ float fast_exp(float x) {
    x = fmaxf(x, -80.f);
    float t = x * 1.4426950408889634f;
    float r = t + 12582912.f;            // round to nearest int (2^23 * 1.5)
    float n = r - 12582912.f;
    float f = t - n;                      // f in [-0.5, 0.5]
    float p = 1.3333558146e-3f;
    p = fmaf(p, f, 9.6179630648e-3f);
    p = fmaf(p, f, 5.5504108664e-2f);
    p = fmaf(p, f, 2.4022650696e-1f);
    p = fmaf(p, f, 6.9314718056e-1f);
    p = fmaf(p, f, 1.0f);
    int e = __float_as_int(r) << 23;      // == n << 23 (mod 2^32)
    return __int_as_float(__float_as_int(p) + e);
}

// ---------------- fp32 -> bf16 (hi, lo) split ------------------------------------
__global__ __launch_bounds__(256) void split_bf16(
    const float* __restrict__ x, __nv_bfloat16* __restrict__ hi,
    __nv_bfloat16* __restrict__ lo, int n4)
{
    int i = blockIdx.x * 256 + threadIdx.x;
    if (i >= n4) return;
    float4 v = *(const float4*)(x + (size_t)i * 4);
    __nv_bfloat16 h0 = __float2bfloat16_rn(v.x);
    __nv_bfloat16 h1 = __float2bfloat16_rn(v.y);
    __nv_bfloat16 h2 = __float2bfloat16_rn(v.z);
    __nv_bfloat16 h3 = __float2bfloat16_rn(v.w);
    __nv_bfloat16 l0 = __float2bfloat16_rn(v.x - __bfloat162float(h0));
    __nv_bfloat16 l1 = __float2bfloat16_rn(v.y - __bfloat162float(h1));
    __nv_bfloat16 l2 = __float2bfloat16_rn(v.z - __bfloat162float(h2));
    __nv_bfloat16 l3 = __float2bfloat16_rn(v.w - __bfloat162float(h3));
    __nv_bfloat162 hh0; hh0.x = h0; hh0.y = h1;
    __nv_bfloat162 hh1; hh1.x = h2; hh1.y = h3;
    __nv_bfloat162 ll0; ll0.x = l0; ll0.y = l1;
    __nv_bfloat162 ll1; ll1.x = l2; ll1.y = l3;
    *(__nv_bfloat162*)(hi + (size_t)i * 4)     = hh0;
    *(__nv_bfloat162*)(hi + (size_t)i * 4 + 2) = hh1;
    *(__nv_bfloat162*)(lo + (size_t)i * 4)     = ll0;
    *(__nv_bfloat162*)(lo + (size_t)i * 4 + 2) = ll1;
}

// ---------------- HMMA GEMM core (bf16 3-pass split) ----------------------------
#define SSTR 40

struct GemmSmem {
    __align__(16) __nv_bfloat16 Ah[128 * SSTR];
    __align__(16) __nv_bfloat16 Al[128 * SSTR];
    __align__(16) __nv_bfloat16 Bh[128 * SSTR];
    __align__(16) __nv_bfloat16 Bl[128 * SSTR];
};

// Computes acc[4][4][4] for the 128x128 tile at (bm, bn).
__device__ __forceinline__ void gemm_mainloop(
    GemmSmem& s,
    const __nv_bfloat16* __restrict__ Ah, const __nv_bfloat16* __restrict__ Al,
    const __nv_bfloat16* __restrict__ Bh, const __nv_bfloat16* __restrict__ Bl,
    int bm, int bn, int wm, int wn, int lane, float acc[4][4][4])
{
    const int tid = threadIdx.x;
    const int r0g = tid >> 2;
    const int r1g = (tid + 256) >> 2;
    const int k0g = (tid & 3) * 8;

    const int a_row = (lane & 15);
    const int a_kof = (lane >> 4) * 8;
    const int b_row = (lane & 7) + (lane >> 4) * 8;
    const int b_kof = ((lane >> 3) & 1) * 8;

    const uint32_t uAh = smem_u32(s.Ah), uAl = smem_u32(s.Al);
    const uint32_t uBh = smem_u32(s.Bh), uBl = smem_u32(s.Bl);

    float4 pAh[2], pAl[2], pBh[2], pBl[2];
    {
        size_t a0 = (size_t)(bm + r0g) * EMBED + k0g;
        size_t a1 = (size_t)(bm + r1g) * EMBED + k0g;
        size_t b0 = (size_t)(bn + r0g) * EMBED + k0g;
        size_t b1 = (size_t)(bn + r1g) * EMBED + k0g;
        pAh[0] = *(const float4*)(Ah + a0); pAh[1] = *(const float4*)(Ah + a1);
        pAl[0] = *(const float4*)(Al + a0); pAl[1] = *(const float4*)(Al + a1);
        pBh[0] = *(const float4*)(Bh + b0); pBh[1] = *(const float4*)(Bh + b1);
        pBl[0] = *(const float4*)(Bl + b0); pBl[1] = *(const float4*)(Bl + b1);
    }

    for (int kb = 0; kb < 32; kb++) {
        *(float4*)&s.Ah[r0g * SSTR + k0g] = pAh[0];
        *(float4*)&s.Ah[r1g * SSTR + k0g] = pAh[1];
        *(float4*)&s.Al[r0g * SSTR + k0g] = pAl[0];
        *(float4*)&s.Al[r1g * SSTR + k0g] = pAl[1];
        *(float4*)&s.Bh[r0g * SSTR + k0g] = pBh[0];
        *(float4*)&s.Bh[r1g * SSTR + k0g] = pBh[1];
        *(float4*)&s.Bl[r0g * SSTR + k0g] = pBl[0];
        *(float4*)&s.Bl[r1g * SSTR + k0g] = pBl[1];
        __syncthreads();

        if (kb < 31) {
            const int kn = (kb + 1) * 32;
            size_t a0 = (size_t)(bm + r0g) * EMBED + kn + k0g;
            size_t a1 = (size_t)(bm + r1g) * EMBED + kn + k0g;
            size_t b0 = (size_t)(bn + r0g) * EMBED + kn + k0g;
            size_t b1 = (size_t)(bn + r1g) * EMBED + kn + k0g;
            pAh[0] = *(const float4*)(Ah + a0); pAh[1] = *(const float4*)(Ah + a1);
            pAl[0] = *(const float4*)(Al + a0); pAl[1] = *(const float4*)(Al + a1);
            pBh[0] = *(const float4*)(Bh + b0); pBh[1] = *(const float4*)(Bh + b1);
            pBl[0] = *(const float4*)(Bl + b0); pBl[1] = *(const float4*)(Bl + b1);
        }

#pragma unroll
        for (int ks = 0; ks < 2; ks++) {
            const int k0 = ks * 16;
            uint32_t fAh[4][4], fAl[4][4], fBh[2][4], fBl[2][4];
#pragma unroll
            for (int mt = 0; mt < 4; mt++) {
                uint32_t off = (uint32_t)((wm + mt * 16 + a_row) * SSTR + k0 + a_kof) * 2;
                LDSM4(fAh[mt], uAh + off);
                LDSM4(fAl[mt], uAl + off);
            }
#pragma unroll
            for (int np = 0; np < 2; np++) {
                uint32_t off = (uint32_t)((wn + np * 16 + b_row) * SSTR + k0 + b_kof) * 2;
                LDSM4(fBh[np], uBh + off);
                LDSM4(fBl[np], uBl + off);
            }
#pragma unroll
            for (int mt = 0; mt < 4; mt++) {
#pragma unroll
                for (int nt = 0; nt < 4; nt++) {
                    const int np = nt >> 1, pr = (nt & 1) * 2;
                    MMA16816(acc[mt][nt], fAh[mt], fBh[np][pr], fBh[np][pr + 1]);
                    MMA16816(acc[mt][nt], fAh[mt], fBl[np][pr], fBl[np][pr + 1]);
                    MMA16816(acc[mt][nt], fAl[mt], fBh[np][pr], fBh[np][pr + 1]);
                }
            }
        }
        __syncthreads();
    }
}

__global__ __launch_bounds__(256, 1) void gemm_hmma(
    const __nv_bfloat16* __restrict__ Ah, const __nv_bfloat16* __restrict__ Al,
    const __nv_bfloat16* __restrict__ Bh, const __nv_bfloat16* __restrict__ Bl,
    const float* __restrict__ bias, float* __restrict__ C)
{
    __shared__ GemmSmem s;
    const int tid = threadIdx.x, wid = tid >> 5, lane = tid & 31;
    const int bm = blockIdx.y * 128, bn = blockIdx.x * 128;
    const int wm = (wid >> 2) * 64, wn = (wid & 3) * 32;

    float acc[4][4][4];
#pragma unroll
    for (int i = 0; i < 4; i++)
#pragma unroll
        for (int j = 0; j < 4; j++)
#pragma unroll
            for (int v = 0; v < 4; v++) acc[i][j][v] = 0.f;

    gemm_mainloop(s, Ah, Al, Bh, Bl, bm, bn, wm, wn, lane, acc);

    const int er = lane >> 2;
    const int ec = (lane & 3) * 2;
#pragma unroll
    for (int nt = 0; nt < 4; nt++) {
        const int gc = bn + wn + nt * 8 + ec;
        const float bx = bias[gc], by = bias[gc + 1];
#pragma unroll
        for (int mt = 0; mt < 4; mt++) {
            const int gr = bm + wm + mt * 16 + er;
            *(float2*)&C[(size_t)gr * EMBED + gc] =
                make_float2(acc[mt][nt][0] + bx, acc[mt][nt][1] + by);
            *(float2*)&C[(size_t)(gr + 8) * EMBED + gc] =
                make_float2(acc[mt][nt][2] + bx, acc[mt][nt][3] + by);
        }
    }
}

__global__ __launch_bounds__(256, 1) void gemm_hmma_f16(
    const __nv_bfloat16* __restrict__ Ah, const __nv_bfloat16* __restrict__ Al,
    const __nv_bfloat16* __restrict__ Bh, const __nv_bfloat16* __restrict__ Bl,
    const float* __restrict__ bias, __half* __restrict__ C, float scale)
{
    __shared__ GemmSmem s;
    const int tid = threadIdx.x, wid = tid >> 5, lane = tid & 31;
    const int bm = blockIdx.y * 128, bn = blockIdx.x * 128;
    const int wm = (wid >> 2) * 64, wn = (wid & 3) * 32;

    float acc[4][4][4];
#pragma unroll
    for (int i = 0; i < 4; i++)
#pragma unroll
        for (int j = 0; j < 4; j++)
#pragma unroll
            for (int v = 0; v < 4; v++) acc[i][j][v] = 0.f;

    gemm_mainloop(s, Ah, Al, Bh, Bl, bm, bn, wm, wn, lane, acc);

    const int er = lane >> 2;
    const int ec = (lane & 3) * 2;
#pragma unroll
    for (int nt = 0; nt < 4; nt++) {
        const int gc = bn + wn + nt * 8 + ec;
        const float bx = bias[gc], by = bias[gc + 1];
#pragma unroll
        for (int mt = 0; mt < 4; mt++) {
            const int gr = bm + wm + mt * 16 + er;
            __half2 v0 = __floats2half2_rn((acc[mt][nt][0] + bx) * scale,
                                           (acc[mt][nt][1] + by) * scale);
            __half2 v1 = __floats2half2_rn((acc[mt][nt][2] + bx) * scale,
                                           (acc[mt][nt][3] + by) * scale);
            *(__half2*)&C[(size_t)gr * EMBED + gc] = v0;
            *(__half2*)&C[(size_t)(gr + 8) * EMBED + gc] = v1;
        }
    }
}

// ---------------- fp16 HMMA flash attention -------------------------------------
// CTA: 128 q-rows x (b,h). 8 warps, each owns 16 rows. 64-key tiles.
// Q pre-scaled by 1/sqrt(DH) at projection. Outputs ctx split to bf16 hi/lo.
__global__ __launch_bounds__(256, 1) void flash_attn_f16(
    const __half* __restrict__ Qh, const __half* __restrict__ Kh,
    const __half* __restrict__ Vh,
    __nv_bfloat16* __restrict__ Chi, __nv_bfloat16* __restrict__ Clo)
{
    __shared__ __align__(16) __half sm[128 * 72];   // Q stage / K(0-63)+V(64-127)

    const int b = blockIdx.z, h = blockIdx.y;
    const int q0 = blockIdx.x * 128;
    const int tid = threadIdx.x, wid = tid >> 5, lane = tid & 31;

    // stage Q tile 128x64, lift to fragments
    for (int u = tid; u < 1024; u += 256) {
        int r = u >> 3, c8 = (u & 7) * 8;
        *(uint4*)&sm[r * 72 + c8] =
            *(const uint4*)(Qh + (size_t)(b * LQ + q0 + r) * EMBED + h * DH + c8);
    }
    __syncthreads();
    uint32_t qf[4][4];
    {
        const int arow = wid * 16 + (lane & 15);
        const int akof = (lane >> 4) * 8;
#pragma unroll
        for (int kt = 0; kt < 4; kt++)
            LDSM4(qf[kt], smem_u32(&sm[arow * 72 + kt * 16 + akof]));
    }
    __syncthreads();

    float acc_o[8][4];
#pragma unroll
    for (int i = 0; i < 8; i++)
#pragma unroll
        for (int j = 0; j < 4; j++) acc_o[i][j] = 0.f;
    float m0 = -1e30f, m1 = -1e30f, l0 = 0.f, l1 = 0.f;

    const int brow = (lane & 7) + ((lane >> 4) << 3);
    const int bkof = ((lane >> 3) & 1) << 3;
    const int vrow = lane & 15;
    const int vcof = (lane >> 4) << 3;

    for (int k0 = 0; k0 < LK; k0 += 64) {
        // load K rows 0-63 and V rows 64-127
        for (int u = tid; u < 512; u += 256) {
            int r = u >> 3, c8 = (u & 7) * 8;
            size_t g = (size_t)(b * LK + k0 + r) * EMBED + h * DH + c8;
            *(uint4*)&sm[r * 72 + c8]        = *(const uint4*)(Kh + g);
            *(uint4*)&sm[(64 + r) * 72 + c8] = *(const uint4*)(Vh + g);
        }
        __syncthreads();

        // S = Q @ K^T  (fp16, fp32 acc)
        float s[8][4];
#pragma unroll
        for (int i = 0; i < 8; i++)
#pragma unroll
            for (int j = 0; j < 4; j++) s[i][j] = 0.f;
#pragma unroll
        for (int kt = 0; kt < 4; kt++) {
#pragma unroll
            for (int np = 0; np < 4; np++) {
                uint32_t kf[4];
                LDSM4(kf, smem_u32(&sm[(np * 16 + brow) * 72 + kt * 16 + bkof]));
                MMAF16(s[2 * np],     qf[kt], kf[0], kf[1]);
                MMAF16(s[2 * np + 1], qf[kt], kf[2], kf[3]);
            }
        }

        // online softmax (rows lane/4 and lane/4+8 of this warp's 16)
        float mx0 = -1e30f, mx1 = -1e30f;
#pragma unroll
        for (int nt = 0; nt < 8; nt++) {
            mx0 = fmaxf(mx0, fmaxf(s[nt][0], s[nt][1]));
            mx1 = fmaxf(mx1, fmaxf(s[nt][2], s[nt][3]));
        }
        mx0 = fmaxf(mx0, __shfl_xor_sync(0xffffffffu, mx0, 1));
        mx0 = fmaxf(mx0, __shfl_xor_sync(0xffffffffu, mx0, 2));
        mx1 = fmaxf(mx1, __shfl_xor_sync(0xffffffffu, mx1, 1));
        mx1 = fmaxf(mx1, __shfl_xor_sync(0xffffffffu, mx1, 2));
        float mn0 = fmaxf(m0, mx0), mn1 = fmaxf(m1, mx1);
        float c0 = fast_exp(m0 - mn0), c1 = fast_exp(m1 - mn1);
        m0 = mn0; m1 = mn1;
        float s0 = 0.f, s1 = 0.f;
#pragma unroll
        for (int nt = 0; nt < 8; nt++) {
            s[nt][0] = fast_exp(s[nt][0] - m0);
            s[nt][1] = fast_exp(s[nt][1] - m0);
            s[nt][2] = fast_exp(s[nt][2] - m1);
            s[nt][3] = fast_exp(s[nt][3] - m1);
            s0 += s[nt][0] + s[nt][1];
            s1 += s[nt][2] + s[nt][3];
        }
        s0 += __shfl_xor_sync(0xffffffffu, s0, 1);
        s0 += __shfl_xor_sync(0xffffffffu, s0, 2);
        s1 += __shfl_xor_sync(0xffffffffu, s1, 1);
        s1 += __shfl_xor_sync(0xffffffffu, s1, 2);
        l0 = l0 * c0 + s0;
        l1 = l1 * c1 + s1;
#pragma unroll
        for (int nt = 0; nt < 8; nt++) {
            acc_o[nt][0] *= c0; acc_o[nt][1] *= c0;
            acc_o[nt][2] *= c1; acc_o[nt][3] *= c1;
        }

        // P fragments (C-frag -> A-frag identity)
        uint32_t pf[4][4];
#pragma unroll
        for (int kt = 0; kt < 4; kt++) {
            pf[kt][0] = pack_half2(s[2 * kt][0],     s[2 * kt][1]);
            pf[kt][1] = pack_half2(s[2 * kt][2],     s[2 * kt][3]);
            pf[kt][2] = pack_half2(s[2 * kt + 1][0], s[2 * kt + 1][1]);
            pf[kt][3] = pack_half2(s[2 * kt + 1][2], s[2 * kt + 1][3]);
        }

        // O += P @ V  (V via ldmatrix.trans)
#pragma unroll
        for (int kt = 0; kt < 4; kt++) {
#pragma unroll
            for (int ng = 0; ng < 4; ng++) {
                uint32_t vf[4];
                LDSM4T(vf, smem_u32(&sm[(64 + kt * 16 + vrow) * 72 + ng * 16 + vcof]));
                MMAF16(acc_o[2 * ng],     pf[kt], vf[0], vf[1]);
                MMAF16(acc_o[2 * ng + 1], pf[kt], vf[2], vf[3]);
            }
        }
        __syncthreads();
    }

    // epilogue: normalize, split fp32 -> bf16 hi/lo
    const float inv0 = 1.f / l0, inv1 = 1.f / l1;
    const int r0 = b * LQ + q0 + wid * 16 + (lane >> 2);   // FIXED: batch offset
    const int cbase = h * DH + (lane & 3) * 2;
#pragma unroll
    for (int nt = 0; nt < 8; nt++) {
        const int col = cbase + nt * 8;
        float a0 = acc_o[nt][0] * inv0, a1 = acc_o[nt][1] * inv0;
        float a2 = acc_o[nt][2] * inv1, a3 = acc_o[nt][3] * inv1;
        __nv_bfloat16 h0 = __float2bfloat16_rn(a0), h1 = __float2bfloat16_rn(a1);
        __nv_bfloat16 h2 = __float2bfloat16_rn(a2), h3 = __float2bfloat16_rn(a3);
        __nv_bfloat162 hi0; hi0.x = h0; hi0.y = h1;
        __nv_bfloat162 hi1; hi1.x = h2; hi1.y = h3;
        __nv_bfloat162 lo0;
        lo0.x = __float2bfloat16_rn(a0 - __bfloat162float(h0));
        lo0.y = __float2bfloat16_rn(a1 - __bfloat162float(h1));
        __nv_bfloat162 lo1;
        lo1.x = __float2bfloat16_rn(a2 - __bfloat162float(h2));
        lo1.y = __float2bfloat16_rn(a3 - __bfloat162float(h3));
        *(__nv_bfloat162*)&Chi[(size_t)r0 * EMBED + col]       = hi0;
        *(__nv_bfloat162*)&Clo[(size_t)r0 * EMBED + col]       = lo0;
        *(__nv_bfloat162*)&Chi[(size_t)(r0 + 8) * EMBED + col] = hi1;
        *(__nv_bfloat162*)&Clo[(size_t)(r0 + 8) * EMBED + col] = lo1;
    }
}

// ---------------- residual + LayerNorm (in-place on out) ------------------------
__global__ __launch_bounds__(256) void resid_ln(
    float* __restrict__ out, const float* __restrict__ qseq,
    const float* __restrict__ gamma, const float* __restrict__ beta)
{
    const int row = blockIdx.x;
    const int tid = threadIdx.x;
    const size_t base = (size_t)row * EMBED + tid * 4;

    float4 o = *(float4*)&out[base];
    float4 q = *(const float4*)&qseq[base];
    float x0 = o.x + q.x, x1 = o.y + q.y, x2 = o.z + q.z, x3 = o.w + q.w;

    float s  = x0 + x1 + x2 + x3;
    float ss = fmaf(x0, x0, fmaf(x1, x1, fmaf(x2, x2, x3 * x3)));
#pragma unroll
    for (int off = 16; off >= 1; off >>= 1) {
        s  += __shfl_xor_sync(0xffffffffu, s, off);
        ss += __shfl_xor_sync(0xffffffffu, ss, off);
    }

    __shared__ float rs[8], rss[8];
    const int warp = tid >> 5, lane = tid & 31;
    if (lane == 0) { rs[warp] = s; rss[warp] = ss; }
    __syncthreads();
    if (tid == 0) {
        float S = 0.f, SS = 0.f;
#pragma unroll
        for (int w = 0; w < 8; w++) { S += rs[w]; SS += rss[w]; }
        rs[0] = S; rss[0] = SS;
    }
    __syncthreads();

    const float mean = rs[0] * (1.0f / EMBED);
    const float var  = rss[0] * (1.0f / EMBED) - mean * mean;
    const float r    = rsqrtf(var + 1e-5f);

    float4 g = *(const float4*)&gamma[tid * 4];
    float4 bt = *(const float4*)&beta[tid * 4];
    float4 y = make_float4((x0 - mean) * r * g.x + bt.x,
                           (x1 - mean) * r * g.y + bt.y,
                           (x2 - mean) * r * g.z + bt.z,
                           (x3 - mean) * r * g.w + bt.w);
    *(float4*)&out[base] = y;
}

// ---------------- launch ---------------------------------------------------------
extern "C" void kernel_launch(void* const* d_in, const int* in_sizes, int n_in,
                              void* d_out, int out_size)
{
    const float* qseq  = (const float*)d_in[0];
    const float* kvseq = (const float*)d_in[1];
    // d_in[2] = prompt_size (unused: reference applies no masking)
    const float* Wq = (const float*)d_in[3];
    const float* bq = (const float*)d_in[4];
    const float* Wk = (const float*)d_in[5];
    const float* bk = (const float*)d_in[6];
    const float* Wv = (const float*)d_in[7];
    const float* bv = (const float*)d_in[8];
    const float* Wo = (const float*)d_in[9];
    const float* bo = (const float*)d_in[10];
    const float* gamma = (const float*)d_in[11];
    const float* beta  = (const float*)d_in[12];
    float* out = (float*)d_out;

    __half *qh, *kh, *vh;
    cudaGetSymbolAddress((void**)&qh, g_Qh);
    cudaGetSymbolAddress((void**)&kh, g_Kh);
    cudaGetSymbolAddress((void**)&vh, g_Vh);

    __nv_bfloat16 *aqh, *aql, *akh, *akl, *ach, *acl;
    __nv_bfloat16 *wqh, *wql, *wkh, *wkl, *wvh, *wvl, *woh, *wol;
    cudaGetSymbolAddress((void**)&aqh, g_Aq_hi);  cudaGetSymbolAddress((void**)&aql, g_Aq_lo);
    cudaGetSymbolAddress((void**)&akh, g_Akv_hi); cudaGetSymbolAddress((void**)&akl, g_Akv_lo);
    cudaGetSymbolAddress((void**)&ach, g_Actx_hi);cudaGetSymbolAddress((void**)&acl, g_Actx_lo);
    cudaGetSymbolAddress((void**)&wqh, g_Wq_hi);  cudaGetSymbolAddress((void**)&wql, g_Wq_lo);
    cudaGetSymbolAddress((void**)&wkh, g_Wk_hi);  cudaGetSymbolAddress((void**)&wkl, g_Wk_lo);
    cudaGetSymbolAddress((void**)&wvh, g_Wv_hi);  cudaGetSymbolAddress((void**)&wvl, g_Wv_lo);
    cudaGetSymbolAddress((void**)&woh, g_Wo_hi);  cudaGetSymbolAddress((void**)&wol, g_Wo_lo);

    const int nA4 = MROWS * EMBED / 4;
    const int nW4 = EMBED * EMBED / 4;

    split_bf16<<<(nA4 + 255) / 256, 256>>>(qseq,  aqh, aql, nA4);
    split_bf16<<<(nA4 + 255) / 256, 256>>>(kvseq, akh, akl, nA4);
    split_bf16<<<(nW4 + 255) / 256, 256>>>(Wq, wqh, wql, nW4);
    split_bf16<<<(nW4 + 255) / 256, 256>>>(Wk, wkh, wkl, nW4);
    split_bf16<<<(nW4 + 255) / 256, 256>>>(Wv, wvh, wvl, nW4);
    split_bf16<<<(nW4 + 255) / 256, 256>>>(Wo, woh, wol, nW4);

    dim3 ggrid(EMBED / 128, MROWS / 128);   // (8, 32)
    gemm_hmma_f16<<<ggrid, 256>>>(aqh, aql, wqh, wql, bq, qh, 0.125f);  // Q pre-scaled
    gemm_hmma_f16<<<ggrid, 256>>>(akh, akl, wkh, wkl, bk, kh, 1.0f);
    gemm_hmma_f16<<<ggrid, 256>>>(akh, akl, wvh, wvl, bv, vh, 1.0f);

    dim3 agrid(LQ / 128, HEADS, BATCH);     // (16, 16, 2)
    flash_attn_f16<<<agrid, 256>>>(qh, kh, vh, ach, acl);

    gemm_hmma<<<ggrid, 256>>>(ach, acl, woh, wol, bo, out);

    resid_ln<<<MROWS, 256>>>(out, qseq, gamma, beta);
}

// round 8
// speedup vs baseline: 5.5365x; 1.4616x over previous
#include <cuda_runtime.h>
#include <cuda_fp16.h>
#include <cstdint>
#include <math.h>

#define EMBED 1024
#define HEADS 16
#define DH 64
#define BATCH 2
#define LQ 2048
#define LK 2048
#define MROWS (BATCH * LQ)   // 4096

// ---------------- scratch (static device globals; no allocation) ----------------
__device__ __half g_Qh[(size_t)MROWS * EMBED];
__device__ __half g_Kh[(size_t)MROWS * EMBED];
__device__ __half g_Vh[(size_t)MROWS * EMBED];
__device__ __half g_Ch[(size_t)MROWS * EMBED];    // attention ctx
__device__ __half g_Xq[(size_t)MROWS * EMBED];    // qseq fp16
__device__ __half g_Xkv[(size_t)MROWS * EMBED];   // kvseq fp16
__device__ __half g_Wqh[(size_t)EMBED * EMBED];
__device__ __half g_Wkh[(size_t)EMBED * EMBED];
__device__ __half g_Wvh[(size_t)EMBED * EMBED];
__device__ __half g_Woh[(size_t)EMBED * EMBED];

// ---------------- PTX helpers (sm_80+ baseline features only) --------------------
__device__ __forceinline__ uint32_t smem_u32(const void* p) {
    uint32_t a;
    asm("{ .reg .u64 t; cvta.to.shared.u64 t, %1; cvt.u32.u64 %0, t; }" : "=r"(a) : "l"(p));
    return a;
}

#define LDSM4(r, addr) \
    asm volatile("ldmatrix.sync.aligned.m8n8.x4.shared.b16 {%0,%1,%2,%3}, [%4];" \
                 : "=r"((r)[0]), "=r"((r)[1]), "=r"((r)[2]), "=r"((r)[3]) : "r"(addr))

#define LDSM4T(r, addr) \
    asm volatile("ldmatrix.sync.aligned.m8n8.x4.trans.shared.b16 {%0,%1,%2,%3}, [%4];" \
                 : "=r"((r)[0]), "=r"((r)[1]), "=r"((r)[2]), "=r"((r)[3]) : "r"(addr))

#define MMAF16(d, a, b0, b1) \
    asm volatile("mma.sync.aligned.m16n8k16.row.col.f32.f16.f16.f32 " \
                 "{%0,%1,%2,%3}, {%4,%5,%6,%7}, {%8,%9}, {%0,%1,%2,%3};" \
                 : "+f"((d)[0]), "+f"((d)[1]), "+f"((d)[2]), "+f"((d)[3]) \
                 : "r"((a)[0]), "r"((a)[1]), "r"((a)[2]), "r"((a)[3]), "r"(b0), "r"(b1))

__device__ __forceinline__ uint32_t pack_half2(float a, float b) {
    __half2 h = __floats2half2_rn(a, b);
    return *(uint32_t*)&h;
}

// exp(x) for x <= 0 on the fma/alu pipes (no MUFU). rel err ~2e-6.
__device__ __forceinline__ float fast_exp(float x) {
    x = fmaxf(x, -80.f);
    float t = x * 1.4426950408889634f;
    float r = t + 12582912.f;            // round to nearest int (2^23 * 1.5)
    float n = r - 12582912.f;
    float f = t - n;                      // f in [-0.5, 0.5]
    float p = 1.3333558146e-3f;
    p = fmaf(p, f, 9.6179630648e-3f);
    p = fmaf(p, f, 5.5504108664e-2f);
    p = fmaf(p, f, 2.4022650696e-1f);
    p = fmaf(p, f, 6.9314718056e-1f);
    p = fmaf(p, f, 1.0f);
    int e = __float_as_int(r) << 23;      // == n << 23 (mod 2^32)
    return __int_as_float(__float_as_int(p) + e);
}

// ---------------- fp32 -> fp16 convert -------------------------------------------
__global__ __launch_bounds__(256) void conv_f16(
    const float* __restrict__ x, __half* __restrict__ y, int n4)
{
    int i = blockIdx.x * 256 + threadIdx.x;
    if (i >= n4) return;
    float4 v = *(const float4*)(x + (size_t)i * 4);
    __half2 a = __floats2half2_rn(v.x, v.y);
    __half2 b = __floats2half2_rn(v.z, v.w);
    *(__half2*)(y + (size_t)i * 4)     = a;
    *(__half2*)(y + (size_t)i * 4 + 2) = b;
}

// ---------------- fp16 single-pass HMMA GEMM -------------------------------------
// C[M=4096, N=1024] = A[M,K] @ B[N,K]^T + bias; tile 128x128, BK=32, double-buffered.
#define SSTR 40

struct SmemF16 {
    __align__(16) __half A[2][128 * SSTR];
    __align__(16) __half B[2][128 * SSTR];
};

__device__ __forceinline__ void mainloop_f16(
    SmemF16& s, const __half* __restrict__ A, const __half* __restrict__ B,
    int bm, int bn, int wm, int wn, int lane, float acc[4][4][4])
{
    const int tid = threadIdx.x;
    const int r0g = tid >> 2;            // 0..63
    const int r1g = r0g + 64;            // 64..127
    const int k0g = (tid & 3) * 8;

    const int a_row = (lane & 15);
    const int a_kof = (lane >> 4) * 8;
    const int b_row = (lane & 7) + (lane >> 4) * 8;
    const int b_kof = ((lane >> 3) & 1) * 8;

    const uint32_t uA0 = smem_u32(s.A[0]), uA1 = smem_u32(s.A[1]);
    const uint32_t uB0 = smem_u32(s.B[0]), uB1 = smem_u32(s.B[1]);

    float4 pA0, pA1, pB0, pB1;

    // stage kb=0 into buffer 0
    pA0 = *(const float4*)(A + (size_t)(bm + r0g) * EMBED + k0g);
    pA1 = *(const float4*)(A + (size_t)(bm + r1g) * EMBED + k0g);
    pB0 = *(const float4*)(B + (size_t)(bn + r0g) * EMBED + k0g);
    pB1 = *(const float4*)(B + (size_t)(bn + r1g) * EMBED + k0g);
    *(float4*)&s.A[0][r0g * SSTR + k0g] = pA0;
    *(float4*)&s.A[0][r1g * SSTR + k0g] = pA1;
    *(float4*)&s.B[0][r0g * SSTR + k0g] = pB0;
    *(float4*)&s.B[0][r1g * SSTR + k0g] = pB1;
    __syncthreads();

    for (int kb = 0; kb < 32; kb++) {
        const int cur = kb & 1, nxt = cur ^ 1;
        if (kb < 31) {
            const int kn = (kb + 1) * 32 + k0g;
            pA0 = *(const float4*)(A + (size_t)(bm + r0g) * EMBED + kn);
            pA1 = *(const float4*)(A + (size_t)(bm + r1g) * EMBED + kn);
            pB0 = *(const float4*)(B + (size_t)(bn + r0g) * EMBED + kn);
            pB1 = *(const float4*)(B + (size_t)(bn + r1g) * EMBED + kn);
        }

        const uint32_t uA = cur ? uA1 : uA0;
        const uint32_t uB = cur ? uB1 : uB0;
#pragma unroll
        for (int ks = 0; ks < 2; ks++) {
            const int k0 = ks * 16;
            uint32_t fA[4][4], fB[2][4];
#pragma unroll
            for (int mt = 0; mt < 4; mt++) {
                uint32_t off = (uint32_t)((wm + mt * 16 + a_row) * SSTR + k0 + a_kof) * 2;
                LDSM4(fA[mt], uA + off);
            }
#pragma unroll
            for (int np = 0; np < 2; np++) {
                uint32_t off = (uint32_t)((wn + np * 16 + b_row) * SSTR + k0 + b_kof) * 2;
                LDSM4(fB[np], uB + off);
            }
#pragma unroll
            for (int mt = 0; mt < 4; mt++) {
#pragma unroll
                for (int nt = 0; nt < 4; nt++) {
                    const int np = nt >> 1, pr = (nt & 1) * 2;
                    MMAF16(acc[mt][nt], fA[mt], fB[np][pr], fB[np][pr + 1]);
                }
            }
        }

        if (kb < 31) {
            __half* sa = cur ? s.A[0] : s.A[1];
            __half* sb = cur ? s.B[0] : s.B[1];
            (void)nxt;
            *(float4*)&sa[r0g * SSTR + k0g] = pA0;
            *(float4*)&sa[r1g * SSTR + k0g] = pA1;
            *(float4*)&sb[r0g * SSTR + k0g] = pB0;
            *(float4*)&sb[r1g * SSTR + k0g] = pB1;
        }
        __syncthreads();
    }
}

// fp16-output variant (with scale, for Q/K/V projections)
__global__ __launch_bounds__(256, 1) void gemm_f16h(
    const __half* __restrict__ A, const __half* __restrict__ B,
    const float* __restrict__ bias, __half* __restrict__ C, float scale)
{
    __shared__ SmemF16 s;
    const int tid = threadIdx.x, wid = tid >> 5, lane = tid & 31;
    const int bm = blockIdx.y * 128, bn = blockIdx.x * 128;
    const int wm = (wid >> 2) * 64, wn = (wid & 3) * 32;

    float acc[4][4][4];
#pragma unroll
    for (int i = 0; i < 4; i++)
#pragma unroll
        for (int j = 0; j < 4; j++)
#pragma unroll
            for (int v = 0; v < 4; v++) acc[i][j][v] = 0.f;

    mainloop_f16(s, A, B, bm, bn, wm, wn, lane, acc);

    const int er = lane >> 2;
    const int ec = (lane & 3) * 2;
#pragma unroll
    for (int nt = 0; nt < 4; nt++) {
        const int gc = bn + wn + nt * 8 + ec;
        const float bx = bias[gc], by = bias[gc + 1];
#pragma unroll
        for (int mt = 0; mt < 4; mt++) {
            const int gr = bm + wm + mt * 16 + er;
            __half2 v0 = __floats2half2_rn((acc[mt][nt][0] + bx) * scale,
                                           (acc[mt][nt][1] + by) * scale);
            __half2 v1 = __floats2half2_rn((acc[mt][nt][2] + bx) * scale,
                                           (acc[mt][nt][3] + by) * scale);
            *(__half2*)&C[(size_t)gr * EMBED + gc] = v0;
            *(__half2*)&C[(size_t)(gr + 8) * EMBED + gc] = v1;
        }
    }
}

// fp32-output variant (O projection)
__global__ __launch_bounds__(256, 1) void gemm_f16f(
    const __half* __restrict__ A, const __half* __restrict__ B,
    const float* __restrict__ bias, float* __restrict__ C)
{
    __shared__ SmemF16 s;
    const int tid = threadIdx.x, wid = tid >> 5, lane = tid & 31;
    const int bm = blockIdx.y * 128, bn = blockIdx.x * 128;
    const int wm = (wid >> 2) * 64, wn = (wid & 3) * 32;

    float acc[4][4][4];
#pragma unroll
    for (int i = 0; i < 4; i++)
#pragma unroll
        for (int j = 0; j < 4; j++)
#pragma unroll
            for (int v = 0; v < 4; v++) acc[i][j][v] = 0.f;

    mainloop_f16(s, A, B, bm, bn, wm, wn, lane, acc);

    const int er = lane >> 2;
    const int ec = (lane & 3) * 2;
#pragma unroll
    for (int nt = 0; nt < 4; nt++) {
        const int gc = bn + wn + nt * 8 + ec;
        const float bx = bias[gc], by = bias[gc + 1];
#pragma unroll
        for (int mt = 0; mt < 4; mt++) {
            const int gr = bm + wm + mt * 16 + er;
            *(float2*)&C[(size_t)gr * EMBED + gc] =
                make_float2(acc[mt][nt][0] + bx, acc[mt][nt][1] + by);
            *(float2*)&C[(size_t)(gr + 8) * EMBED + gc] =
                make_float2(acc[mt][nt][2] + bx, acc[mt][nt][3] + by);
        }
    }
}

// ---------------- fp16 HMMA flash attention -------------------------------------
// CTA: 128 q-rows x (b,h). 8 warps, each owns 16 rows. 64-key tiles.
// Q pre-scaled by 1/sqrt(DH) at projection. Outputs ctx as fp16.
__global__ __launch_bounds__(256, 1) void flash_attn_f16(
    const __half* __restrict__ Qh, const __half* __restrict__ Kh,
    const __half* __restrict__ Vh, __half* __restrict__ Ch)
{
    __shared__ __align__(16) __half sm[128 * 72];   // Q stage / K(0-63)+V(64-127)

    const int b = blockIdx.z, h = blockIdx.y;
    const int q0 = blockIdx.x * 128;
    const int tid = threadIdx.x, wid = tid >> 5, lane = tid & 31;

    // stage Q tile 128x64, lift to fragments
    for (int u = tid; u < 1024; u += 256) {
        int r = u >> 3, c8 = (u & 7) * 8;
        *(uint4*)&sm[r * 72 + c8] =
            *(const uint4*)(Qh + (size_t)(b * LQ + q0 + r) * EMBED + h * DH + c8);
    }
    __syncthreads();
    uint32_t qf[4][4];
    {
        const int arow = wid * 16 + (lane & 15);
        const int akof = (lane >> 4) * 8;
#pragma unroll
        for (int kt = 0; kt < 4; kt++)
            LDSM4(qf[kt], smem_u32(&sm[arow * 72 + kt * 16 + akof]));
    }
    __syncthreads();

    float acc_o[8][4];
#pragma unroll
    for (int i = 0; i < 8; i++)
#pragma unroll
        for (int j = 0; j < 4; j++) acc_o[i][j] = 0.f;
    float m0 = -1e30f, m1 = -1e30f, l0 = 0.f, l1 = 0.f;

    const int brow = (lane & 7) + ((lane >> 4) << 3);
    const int bkof = ((lane >> 3) & 1) << 3;
    const int vrow = lane & 15;
    const int vcof = (lane >> 4) << 3;

    for (int k0 = 0; k0 < LK; k0 += 64) {
        // load K rows 0-63 and V rows 64-127
        for (int u = tid; u < 512; u += 256) {
            int r = u >> 3, c8 = (u & 7) * 8;
            size_t g = (size_t)(b * LK + k0 + r) * EMBED + h * DH + c8;
            *(uint4*)&sm[r * 72 + c8]        = *(const uint4*)(Kh + g);
            *(uint4*)&sm[(64 + r) * 72 + c8] = *(const uint4*)(Vh + g);
        }
        __syncthreads();

        // S = Q @ K^T  (fp16, fp32 acc)
        float s[8][4];
#pragma unroll
        for (int i = 0; i < 8; i++)
#pragma unroll
            for (int j = 0; j < 4; j++) s[i][j] = 0.f;
#pragma unroll
        for (int kt = 0; kt < 4; kt++) {
#pragma unroll
            for (int np = 0; np < 4; np++) {
                uint32_t kf[4];
                LDSM4(kf, smem_u32(&sm[(np * 16 + brow) * 72 + kt * 16 + bkof]));
                MMAF16(s[2 * np],     qf[kt], kf[0], kf[1]);
                MMAF16(s[2 * np + 1], qf[kt], kf[2], kf[3]);
            }
        }

        // online softmax (rows lane/4 and lane/4+8 of this warp's 16)
        float mx0 = -1e30f, mx1 = -1e30f;
#pragma unroll
        for (int nt = 0; nt < 8; nt++) {
            mx0 = fmaxf(mx0, fmaxf(s[nt][0], s[nt][1]));
            mx1 = fmaxf(mx1, fmaxf(s[nt][2], s[nt][3]));
        }
        mx0 = fmaxf(mx0, __shfl_xor_sync(0xffffffffu, mx0, 1));
        mx0 = fmaxf(mx0, __shfl_xor_sync(0xffffffffu, mx0, 2));
        mx1 = fmaxf(mx1, __shfl_xor_sync(0xffffffffu, mx1, 1));
        mx1 = fmaxf(mx1, __shfl_xor_sync(0xffffffffu, mx1, 2));
        float mn0 = fmaxf(m0, mx0), mn1 = fmaxf(m1, mx1);
        float c0 = fast_exp(m0 - mn0), c1 = fast_exp(m1 - mn1);
        m0 = mn0; m1 = mn1;
        float s0 = 0.f, s1 = 0.f;
#pragma unroll
        for (int nt = 0; nt < 8; nt++) {
            s[nt][0] = fast_exp(s[nt][0] - m0);
            s[nt][1] = fast_exp(s[nt][1] - m0);
            s[nt][2] = fast_exp(s[nt][2] - m1);
            s[nt][3] = fast_exp(s[nt][3] - m1);
            s0 += s[nt][0] + s[nt][1];
            s1 += s[nt][2] + s[nt][3];
        }
        s0 += __shfl_xor_sync(0xffffffffu, s0, 1);
        s0 += __shfl_xor_sync(0xffffffffu, s0, 2);
        s1 += __shfl_xor_sync(0xffffffffu, s1, 1);
        s1 += __shfl_xor_sync(0xffffffffu, s1, 2);
        l0 = l0 * c0 + s0;
        l1 = l1 * c1 + s1;
#pragma unroll
        for (int nt = 0; nt < 8; nt++) {
            acc_o[nt][0] *= c0; acc_o[nt][1] *= c0;
            acc_o[nt][2] *= c1; acc_o[nt][3] *= c1;
        }

        // P fragments (C-frag -> A-frag identity)
        uint32_t pf[4][4];
#pragma unroll
        for (int kt = 0; kt < 4; kt++) {
            pf[kt][0] = pack_half2(s[2 * kt][0],     s[2 * kt][1]);
            pf[kt][1] = pack_half2(s[2 * kt][2],     s[2 * kt][3]);
            pf[kt][2] = pack_half2(s[2 * kt + 1][0], s[2 * kt + 1][1]);
            pf[kt][3] = pack_half2(s[2 * kt + 1][2], s[2 * kt + 1][3]);
        }

        // O += P @ V  (V via ldmatrix.trans)
#pragma unroll
        for (int kt = 0; kt < 4; kt++) {
#pragma unroll
            for (int ng = 0; ng < 4; ng++) {
                uint32_t vf[4];
                LDSM4T(vf, smem_u32(&sm[(64 + kt * 16 + vrow) * 72 + ng * 16 + vcof]));
                MMAF16(acc_o[2 * ng],     pf[kt], vf[0], vf[1]);
                MMAF16(acc_o[2 * ng + 1], pf[kt], vf[2], vf[3]);
            }
        }
        __syncthreads();
    }

    // epilogue: normalize, write fp16 ctx
    const float inv0 = 1.f / l0, inv1 = 1.f / l1;
    const int r0 = b * LQ + q0 + wid * 16 + (lane >> 2);
    const int cbase = h * DH + (lane & 3) * 2;
#pragma unroll
    for (int nt = 0; nt < 8; nt++) {
        const int col = cbase + nt * 8;
        *(__half2*)&Ch[(size_t)r0 * EMBED + col] =
            __floats2half2_rn(acc_o[nt][0] * inv0, acc_o[nt][1] * inv0);
        *(__half2*)&Ch[(size_t)(r0 + 8) * EMBED + col] =
            __floats2half2_rn(acc_o[nt][2] * inv1, acc_o[nt][3] * inv1);
    }
}

// ---------------- residual + LayerNorm (in-place on out) ------------------------
__global__ __launch_bounds__(256) void resid_ln(
    float* __restrict__ out, const float* __restrict__ qseq,
    const float* __restrict__ gamma, const float* __restrict__ beta)
{
    const int row = blockIdx.x;
    const int tid = threadIdx.x;
    const size_t base = (size_t)row * EMBED + tid * 4;

    float4 o = *(float4*)&out[base];
    float4 q = *(const float4*)&qseq[base];
    float x0 = o.x + q.x, x1 = o.y + q.y, x2 = o.z + q.z, x3 = o.w + q.w;

    float s  = x0 + x1 + x2 + x3;
    float ss = fmaf(x0, x0, fmaf(x1, x1, fmaf(x2, x2, x3 * x3)));
#pragma unroll
    for (int off = 16; off >= 1; off >>= 1) {
        s  += __shfl_xor_sync(0xffffffffu, s, off);
        ss += __shfl_xor_sync(0xffffffffu, ss, off);
    }

    __shared__ float rs[8], rss[8];
    const int warp = tid >> 5, lane = tid & 31;
    if (lane == 0) { rs[warp] = s; rss[warp] = ss; }
    __syncthreads();
    if (tid == 0) {
        float S = 0.f, SS = 0.f;
#pragma unroll
        for (int w = 0; w < 8; w++) { S += rs[w]; SS += rss[w]; }
        rs[0] = S; rss[0] = SS;
    }
    __syncthreads();

    const float mean = rs[0] * (1.0f / EMBED);
    const float var  = rss[0] * (1.0f / EMBED) - mean * mean;
    const float r    = rsqrtf(var + 1e-5f);

    float4 g = *(const float4*)&gamma[tid * 4];
    float4 bt = *(const float4*)&beta[tid * 4];
    float4 y = make_float4((x0 - mean) * r * g.x + bt.x,
                           (x1 - mean) * r * g.y + bt.y,
                           (x2 - mean) * r * g.z + bt.z,
                           (x3 - mean) * r * g.w + bt.w);
    *(float4*)&out[base] = y;
}

// ---------------- launch ---------------------------------------------------------
extern "C" void kernel_launch(void* const* d_in, const int* in_sizes, int n_in,
                              void* d_out, int out_size)
{
    const float* qseq  = (const float*)d_in[0];
    const float* kvseq = (const float*)d_in[1];
    // d_in[2] = prompt_size (unused: reference applies no masking)
    const float* Wq = (const float*)d_in[3];
    const float* bq = (const float*)d_in[4];
    const float* Wk = (const float*)d_in[5];
    const float* bk = (const float*)d_in[6];
    const float* Wv = (const float*)d_in[7];
    const float* bv = (const float*)d_in[8];
    const float* Wo = (const float*)d_in[9];
    const float* bo = (const float*)d_in[10];
    const float* gamma = (const float*)d_in[11];
    const float* beta  = (const float*)d_in[12];
    float* out = (float*)d_out;

    __half *qh, *kh, *vh, *ch, *xq, *xkv, *wq, *wk, *wv, *wo;
    cudaGetSymbolAddress((void**)&qh, g_Qh);
    cudaGetSymbolAddress((void**)&kh, g_Kh);
    cudaGetSymbolAddress((void**)&vh, g_Vh);
    cudaGetSymbolAddress((void**)&ch, g_Ch);
    cudaGetSymbolAddress((void**)&xq, g_Xq);
    cudaGetSymbolAddress((void**)&xkv, g_Xkv);
    cudaGetSymbolAddress((void**)&wq, g_Wqh);
    cudaGetSymbolAddress((void**)&wk, g_Wkh);
    cudaGetSymbolAddress((void**)&wv, g_Wvh);
    cudaGetSymbolAddress((void**)&wo, g_Woh);

    const int nA4 = MROWS * EMBED / 4;
    const int nW4 = EMBED * EMBED / 4;

    conv_f16<<<(nA4 + 255) / 256, 256>>>(qseq,  xq,  nA4);
    conv_f16<<<(nA4 + 255) / 256, 256>>>(kvseq, xkv, nA4);
    conv_f16<<<(nW4 + 255) / 256, 256>>>(Wq, wq, nW4);
    conv_f16<<<(nW4 + 255) / 256, 256>>>(Wk, wk, nW4);
    conv_f16<<<(nW4 + 255) / 256, 256>>>(Wv, wv, nW4);
    conv_f16<<<(nW4 + 255) / 256, 256>>>(Wo, wo, nW4);

    dim3 ggrid(EMBED / 128, MROWS / 128);   // (8, 32)
    gemm_f16h<<<ggrid, 256>>>(xq,  wq, bq, qh, 0.125f);   // Q pre-scaled by 1/sqrt(DH)
    gemm_f16h<<<ggrid, 256>>>(xkv, wk, bk, kh, 1.0f);
    gemm_f16h<<<ggrid, 256>>>(xkv, wv, bv, vh, 1.0f);

    dim3 agrid(LQ / 128, HEADS, BATCH);     // (16, 16, 2)
    flash_attn_f16<<<agrid, 256>>>(qh, kh, vh, ch);

    gemm_f16f<<<ggrid, 256>>>(ch, wo, bo, out);

    resid_ln<<<MROWS, 256>>>(out, qseq, gamma, beta);
}

// round 9
// speedup vs baseline: 6.6484x; 1.2008x over previous
#include <cuda_runtime.h>
#include <cuda_fp16.h>
#include <cstdint>
#include <math.h>

#define EMBED 1024
#define HEADS 16
#define DH 64
#define BATCH 2
#define LQ 2048
#define LK 2048
#define MROWS (BATCH * LQ)   // 4096

// ---------------- scratch (static device globals; no allocation) ----------------
__device__ __half g_Qh[(size_t)MROWS * EMBED];
__device__ __half g_Kh[(size_t)MROWS * EMBED];
__device__ __half g_Vh[(size_t)MROWS * EMBED];
__device__ __half g_Ch[(size_t)MROWS * EMBED];    // attention ctx
__device__ __half g_Xq[(size_t)MROWS * EMBED];    // qseq fp16
__device__ __half g_Xkv[(size_t)MROWS * EMBED];   // kvseq fp16
__device__ __half g_Wqh[(size_t)EMBED * EMBED];
__device__ __half g_Wkh[(size_t)EMBED * EMBED];
__device__ __half g_Wvh[(size_t)EMBED * EMBED];
__device__ __half g_Woh[(size_t)EMBED * EMBED];

// ---------------- PTX helpers (sm_80+ baseline features only) --------------------
__device__ __forceinline__ uint32_t smem_u32(const void* p) {
    uint32_t a;
    asm("{ .reg .u64 t; cvta.to.shared.u64 t, %1; cvt.u32.u64 %0, t; }" : "=r"(a) : "l"(p));
    return a;
}

#define LDSM4(r, addr) \
    asm volatile("ldmatrix.sync.aligned.m8n8.x4.shared.b16 {%0,%1,%2,%3}, [%4];" \
                 : "=r"((r)[0]), "=r"((r)[1]), "=r"((r)[2]), "=r"((r)[3]) : "r"(addr))

#define LDSM4T(r, addr) \
    asm volatile("ldmatrix.sync.aligned.m8n8.x4.trans.shared.b16 {%0,%1,%2,%3}, [%4];" \
                 : "=r"((r)[0]), "=r"((r)[1]), "=r"((r)[2]), "=r"((r)[3]) : "r"(addr))

#define MMAF16(d, a, b0, b1) \
    asm volatile("mma.sync.aligned.m16n8k16.row.col.f32.f16.f16.f32 " \
                 "{%0,%1,%2,%3}, {%4,%5,%6,%7}, {%8,%9}, {%0,%1,%2,%3};" \
                 : "+f"((d)[0]), "+f"((d)[1]), "+f"((d)[2]), "+f"((d)[3]) \
                 : "r"((a)[0]), "r"((a)[1]), "r"((a)[2]), "r"((a)[3]), "r"(b0), "r"(b1))

#define CP16(dst, src) \
    asm volatile("cp.async.cg.shared.global [%0], [%1], 16;" :: "r"(dst), "l"(src) : "memory")
#define CP_COMMIT() asm volatile("cp.async.commit_group;" ::: "memory")
#define CP_WAIT1()  asm volatile("cp.async.wait_group 1;" ::: "memory")
#define CP_WAIT0()  asm volatile("cp.async.wait_group 0;" ::: "memory")

__device__ __forceinline__ uint32_t pack_half2(float a, float b) {
    __half2 h = __floats2half2_rn(a, b);
    return *(uint32_t*)&h;
}

// exp(x) for x <= 0 on the fma/alu pipes (no MUFU). rel err ~2e-6.
__device__ __forceinline__ float fast_exp(float x) {
    x = fmaxf(x, -80.f);
    float t = x * 1.4426950408889634f;
    float r = t + 12582912.f;            // round to nearest int (2^23 * 1.5)
    float n = r - 12582912.f;
    float f = t - n;                      // f in [-0.5, 0.5]
    float p = 1.3333558146e-3f;
    p = fmaf(p, f, 9.6179630648e-3f);
    p = fmaf(p, f, 5.5504108664e-2f);
    p = fmaf(p, f, 2.4022650696e-1f);
    p = fmaf(p, f, 6.9314718056e-1f);
    p = fmaf(p, f, 1.0f);
    int e = __float_as_int(r) << 23;      // == n << 23 (mod 2^32)
    return __int_as_float(__float_as_int(p) + e);
}

// ---------------- fused fp32 -> fp16 convert (all 6 tensors, 1 launch) ----------
#define NA4 (MROWS * EMBED / 4)   // 1048576
#define NW4 (EMBED * EMBED / 4)   // 262144

__global__ __launch_bounds__(256) void conv_all(
    const float* __restrict__ qseq, const float* __restrict__ kvseq,
    const float* __restrict__ Wq, const float* __restrict__ Wk,
    const float* __restrict__ Wv, const float* __restrict__ Wo,
    __half* __restrict__ xq, __half* __restrict__ xkv,
    __half* __restrict__ wq, __half* __restrict__ wk,
    __half* __restrict__ wv, __half* __restrict__ wo)
{
    int i = blockIdx.x * 256 + threadIdx.x;
    const float* src;
    __half* dst;
    int off;
    if (i < NA4)            { src = qseq;  dst = xq;  off = i; }
    else if (i < 2 * NA4)   { src = kvseq; dst = xkv; off = i - NA4; }
    else {
        int j = i - 2 * NA4;
        int w = j / NW4;
        off = j - w * NW4;
        src = (w == 0) ? Wq : (w == 1) ? Wk : (w == 2) ? Wv : Wo;
        dst = (w == 0) ? wq : (w == 1) ? wk : (w == 2) ? wv : wo;
    }
    float4 v = ((const float4*)src)[off];
    *(__half2*)(dst + (size_t)off * 4)     = __floats2half2_rn(v.x, v.y);
    *(__half2*)(dst + (size_t)off * 4 + 2) = __floats2half2_rn(v.z, v.w);
}

// ---------------- fp16 HMMA GEMM, cp.async 2-stage pipeline ----------------------
// C[4096, 1024] = A @ B^T + bias; tile 128x128, BK=32.
#define SSTR 40
#define ABUF_B (128 * SSTR * 2)    // 10240 bytes per stage buffer

struct SmemF16 {
    __align__(16) __half A[2][128 * SSTR];
    __align__(16) __half B[2][128 * SSTR];
};

__device__ __forceinline__ void mainloop_f16(
    SmemF16& s, const __half* __restrict__ A, const __half* __restrict__ B,
    int bm, int bn, int wm, int wn, int lane, float acc[4][4][4])
{
    const int tid = threadIdx.x;
    const int r0g = tid >> 2;            // 0..63
    const int r1g = r0g + 64;            // 64..127
    const int k0g = (tid & 3) * 8;

    const int a_row = (lane & 15);
    const int a_kof = (lane >> 4) * 8;
    const int b_row = (lane & 7) + (lane >> 4) * 8;
    const int b_kof = ((lane >> 3) & 1) * 8;

    const uint32_t base = smem_u32(&s);
    const uint32_t aoff0 = (uint32_t)(r0g * SSTR + k0g) * 2;
    const uint32_t aoff1 = (uint32_t)(r1g * SSTR + k0g) * 2;

    const __half* gA = A + (size_t)(bm + r0g) * EMBED + k0g;
    const __half* gB = B + (size_t)(bn + r0g) * EMBED + k0g;

    // prologue: stage 0 into buffer 0
    CP16(base + aoff0, gA);
    CP16(base + aoff1, gA + 64 * EMBED);
    CP16(base + 2 * ABUF_B + aoff0, gB);
    CP16(base + 2 * ABUF_B + aoff1, gB + 64 * EMBED);
    CP_COMMIT();

    for (int kb = 0; kb < 32; kb++) {
        const int cur = kb & 1;
        if (kb < 31) {
            const int nb = cur ^ 1;
            const int kn = (kb + 1) * 32;
            CP16(base + nb * ABUF_B + aoff0, gA + kn);
            CP16(base + nb * ABUF_B + aoff1, gA + kn + 64 * EMBED);
            CP16(base + 2 * ABUF_B + nb * ABUF_B + aoff0, gB + kn);
            CP16(base + 2 * ABUF_B + nb * ABUF_B + aoff1, gB + kn + 64 * EMBED);
            CP_COMMIT();
            CP_WAIT1();
        } else {
            CP_WAIT0();
        }
        __syncthreads();

        const uint32_t uA = base + cur * ABUF_B;
        const uint32_t uB = base + 2 * ABUF_B + cur * ABUF_B;
#pragma unroll
        for (int ks = 0; ks < 2; ks++) {
            const int k0 = ks * 16;
            uint32_t fA[4][4], fB[2][4];
#pragma unroll
            for (int mt = 0; mt < 4; mt++) {
                uint32_t off = (uint32_t)((wm + mt * 16 + a_row) * SSTR + k0 + a_kof) * 2;
                LDSM4(fA[mt], uA + off);
            }
#pragma unroll
            for (int np = 0; np < 2; np++) {
                uint32_t off = (uint32_t)((wn + np * 16 + b_row) * SSTR + k0 + b_kof) * 2;
                LDSM4(fB[np], uB + off);
            }
#pragma unroll
            for (int mt = 0; mt < 4; mt++) {
#pragma unroll
                for (int nt = 0; nt < 4; nt++) {
                    const int np = nt >> 1, pr = (nt & 1) * 2;
                    MMAF16(acc[mt][nt], fA[mt], fB[np][pr], fB[np][pr + 1]);
                }
            }
        }
        __syncthreads();
    }
}

// Fused Q/K/V projections: grid.z selects which.
__global__ __launch_bounds__(256, 1) void gemm_qkv(
    const __half* __restrict__ xq, const __half* __restrict__ xkv,
    const __half* __restrict__ wq, const __half* __restrict__ wk,
    const __half* __restrict__ wv,
    const float* __restrict__ bq, const float* __restrict__ bk,
    const float* __restrict__ bv,
    __half* __restrict__ qh, __half* __restrict__ kh, __half* __restrict__ vh)
{
    __shared__ SmemF16 s;
    const int z = blockIdx.z;
    const __half* A = (z == 0) ? xq : xkv;
    const __half* B = (z == 0) ? wq : (z == 1) ? wk : wv;
    const float* bias = (z == 0) ? bq : (z == 1) ? bk : bv;
    __half* C = (z == 0) ? qh : (z == 1) ? kh : vh;
    const float scale = (z == 0) ? 0.125f : 1.0f;

    const int tid = threadIdx.x, wid = tid >> 5, lane = tid & 31;
    const int bm = blockIdx.y * 128, bn = blockIdx.x * 128;
    const int wm = (wid >> 2) * 64, wn = (wid & 3) * 32;

    float acc[4][4][4];
#pragma unroll
    for (int i = 0; i < 4; i++)
#pragma unroll
        for (int j = 0; j < 4; j++)
#pragma unroll
            for (int v = 0; v < 4; v++) acc[i][j][v] = 0.f;

    mainloop_f16(s, A, B, bm, bn, wm, wn, lane, acc);

    const int er = lane >> 2;
    const int ec = (lane & 3) * 2;
#pragma unroll
    for (int nt = 0; nt < 4; nt++) {
        const int gc = bn + wn + nt * 8 + ec;
        const float bx = bias[gc], by = bias[gc + 1];
#pragma unroll
        for (int mt = 0; mt < 4; mt++) {
            const int gr = bm + wm + mt * 16 + er;
            *(__half2*)&C[(size_t)gr * EMBED + gc] =
                __floats2half2_rn((acc[mt][nt][0] + bx) * scale,
                                  (acc[mt][nt][1] + by) * scale);
            *(__half2*)&C[(size_t)(gr + 8) * EMBED + gc] =
                __floats2half2_rn((acc[mt][nt][2] + bx) * scale,
                                  (acc[mt][nt][3] + by) * scale);
        }
    }
}

// fp32-output variant (O projection)
__global__ __launch_bounds__(256, 1) void gemm_f16f(
    const __half* __restrict__ A, const __half* __restrict__ B,
    const float* __restrict__ bias, float* __restrict__ C)
{
    __shared__ SmemF16 s;
    const int tid = threadIdx.x, wid = tid >> 5, lane = tid & 31;
    const int bm = blockIdx.y * 128, bn = blockIdx.x * 128;
    const int wm = (wid >> 2) * 64, wn = (wid & 3) * 32;

    float acc[4][4][4];
#pragma unroll
    for (int i = 0; i < 4; i++)
#pragma unroll
        for (int j = 0; j < 4; j++)
#pragma unroll
            for (int v = 0; v < 4; v++) acc[i][j][v] = 0.f;

    mainloop_f16(s, A, B, bm, bn, wm, wn, lane, acc);

    const int er = lane >> 2;
    const int ec = (lane & 3) * 2;
#pragma unroll
    for (int nt = 0; nt < 4; nt++) {
        const int gc = bn + wn + nt * 8 + ec;
        const float bx = bias[gc], by = bias[gc + 1];
#pragma unroll
        for (int mt = 0; mt < 4; mt++) {
            const int gr = bm + wm + mt * 16 + er;
            *(float2*)&C[(size_t)gr * EMBED + gc] =
                make_float2(acc[mt][nt][0] + bx, acc[mt][nt][1] + by);
            *(float2*)&C[(size_t)(gr + 8) * EMBED + gc] =
                make_float2(acc[mt][nt][2] + bx, acc[mt][nt][3] + by);
        }
    }
}

// ---------------- fp16 HMMA flash attention, cp.async 2-stage K/V ----------------
// CTA: 128 q-rows x (b,h). 8 warps, each owns 16 rows. 64-key tiles.
#define KVBUF_B (128 * 72 * 2)     // 18432 bytes per stage (K rows 0-63, V rows 64-127)

__global__ __launch_bounds__(256, 1) void flash_attn_f16(
    const __half* __restrict__ Qh, const __half* __restrict__ Kh,
    const __half* __restrict__ Vh, __half* __restrict__ Ch)
{
    __shared__ __align__(16) __half smKV[2][128 * 72];

    const int b = blockIdx.z, h = blockIdx.y;
    const int q0 = blockIdx.x * 128;
    const int tid = threadIdx.x, wid = tid >> 5, lane = tid & 31;

    // stage Q tile 128x64 into buffer 0, lift to fragments
    for (int u = tid; u < 1024; u += 256) {
        int r = u >> 3, c8 = (u & 7) * 8;
        *(uint4*)&smKV[0][r * 72 + c8] =
            *(const uint4*)(Qh + (size_t)(b * LQ + q0 + r) * EMBED + h * DH + c8);
    }
    __syncthreads();
    uint32_t qf[4][4];
    {
        const int arow = wid * 16 + (lane & 15);
        const int akof = (lane >> 4) * 8;
#pragma unroll
        for (int kt = 0; kt < 4; kt++)
            LDSM4(qf[kt], smem_u32(&smKV[0][arow * 72 + kt * 16 + akof]));
    }
    __syncthreads();

    const uint32_t kvbase = smem_u32(smKV);
    // per-thread copy coordinates (2 chunks: rows r and r+32 pattern via u, u+256)
    const int cr0 = tid >> 3;                 // 0..31
    const int cr1 = cr0 + 32;                 // 32..63
    const int cc8 = (tid & 7) * 8;

    // prologue: tile 0 into buffer 0
    {
        size_t g0 = (size_t)(b * LK + cr0) * EMBED + h * DH + cc8;
        size_t g1 = (size_t)(b * LK + cr1) * EMBED + h * DH + cc8;
        CP16(kvbase + (uint32_t)(cr0 * 72 + cc8) * 2, Kh + g0);
        CP16(kvbase + (uint32_t)((64 + cr0) * 72 + cc8) * 2, Vh + g0);
        CP16(kvbase + (uint32_t)(cr1 * 72 + cc8) * 2, Kh + g1);
        CP16(kvbase + (uint32_t)((64 + cr1) * 72 + cc8) * 2, Vh + g1);
        CP_COMMIT();
    }

    float acc_o[8][4];
#pragma unroll
    for (int i = 0; i < 8; i++)
#pragma unroll
        for (int j = 0; j < 4; j++) acc_o[i][j] = 0.f;
    float m0 = -1e30f, m1 = -1e30f, l0 = 0.f, l1 = 0.f;

    const int brow = (lane & 7) + ((lane >> 4) << 3);
    const int bkof = ((lane >> 3) & 1) << 3;
    const int vrow = lane & 15;
    const int vcof = (lane >> 4) << 3;

    for (int t = 0; t < LK / 64; t++) {
        const int cur = t & 1;
        if (t < LK / 64 - 1) {
            const int nb = cur ^ 1;
            const int k0n = (t + 1) * 64;
            size_t g0 = (size_t)(b * LK + k0n + cr0) * EMBED + h * DH + cc8;
            size_t g1 = (size_t)(b * LK + k0n + cr1) * EMBED + h * DH + cc8;
            CP16(kvbase + nb * KVBUF_B + (uint32_t)(cr0 * 72 + cc8) * 2, Kh + g0);
            CP16(kvbase + nb * KVBUF_B + (uint32_t)((64 + cr0) * 72 + cc8) * 2, Vh + g0);
            CP16(kvbase + nb * KVBUF_B + (uint32_t)(cr1 * 72 + cc8) * 2, Kh + g1);
            CP16(kvbase + nb * KVBUF_B + (uint32_t)((64 + cr1) * 72 + cc8) * 2, Vh + g1);
            CP_COMMIT();
            CP_WAIT1();
        } else {
            CP_WAIT0();
        }
        __syncthreads();
        const uint32_t ub = kvbase + cur * KVBUF_B;

        // S = Q @ K^T  (fp16, fp32 acc)
        float s[8][4];
#pragma unroll
        for (int i = 0; i < 8; i++)
#pragma unroll
            for (int j = 0; j < 4; j++) s[i][j] = 0.f;
#pragma unroll
        for (int kt = 0; kt < 4; kt++) {
#pragma unroll
            for (int np = 0; np < 4; np++) {
                uint32_t kf[4];
                LDSM4(kf, ub + (uint32_t)((np * 16 + brow) * 72 + kt * 16 + bkof) * 2);
                MMAF16(s[2 * np],     qf[kt], kf[0], kf[1]);
                MMAF16(s[2 * np + 1], qf[kt], kf[2], kf[3]);
            }
        }

        // online softmax (rows lane/4 and lane/4+8 of this warp's 16)
        float mx0 = -1e30f, mx1 = -1e30f;
#pragma unroll
        for (int nt = 0; nt < 8; nt++) {
            mx0 = fmaxf(mx0, fmaxf(s[nt][0], s[nt][1]));
            mx1 = fmaxf(mx1, fmaxf(s[nt][2], s[nt][3]));
        }
        mx0 = fmaxf(mx0, __shfl_xor_sync(0xffffffffu, mx0, 1));
        mx0 = fmaxf(mx0, __shfl_xor_sync(0xffffffffu, mx0, 2));
        mx1 = fmaxf(mx1, __shfl_xor_sync(0xffffffffu, mx1, 1));
        mx1 = fmaxf(mx1, __shfl_xor_sync(0xffffffffu, mx1, 2));
        float mn0 = fmaxf(m0, mx0), mn1 = fmaxf(m1, mx1);
        float c0 = fast_exp(m0 - mn0), c1 = fast_exp(m1 - mn1);
        m0 = mn0; m1 = mn1;
        float s0 = 0.f, s1 = 0.f;
#pragma unroll
        for (int nt = 0; nt < 8; nt++) {
            s[nt][0] = fast_exp(s[nt][0] - m0);
            s[nt][1] = fast_exp(s[nt][1] - m0);
            s[nt][2] = fast_exp(s[nt][2] - m1);
            s[nt][3] = fast_exp(s[nt][3] - m1);
            s0 += s[nt][0] + s[nt][1];
            s1 += s[nt][2] + s[nt][3];
        }
        s0 += __shfl_xor_sync(0xffffffffu, s0, 1);
        s0 += __shfl_xor_sync(0xffffffffu, s0, 2);
        s1 += __shfl_xor_sync(0xffffffffu, s1, 1);
        s1 += __shfl_xor_sync(0xffffffffu, s1, 2);
        l0 = l0 * c0 + s0;
        l1 = l1 * c1 + s1;
#pragma unroll
        for (int nt = 0; nt < 8; nt++) {
            acc_o[nt][0] *= c0; acc_o[nt][1] *= c0;
            acc_o[nt][2] *= c1; acc_o[nt][3] *= c1;
        }

        // P fragments (C-frag -> A-frag identity)
        uint32_t pf[4][4];
#pragma unroll
        for (int kt = 0; kt < 4; kt++) {
            pf[kt][0] = pack_half2(s[2 * kt][0],     s[2 * kt][1]);
            pf[kt][1] = pack_half2(s[2 * kt][2],     s[2 * kt][3]);
            pf[kt][2] = pack_half2(s[2 * kt + 1][0], s[2 * kt + 1][1]);
            pf[kt][3] = pack_half2(s[2 * kt + 1][2], s[2 * kt + 1][3]);
        }

        // O += P @ V  (V via ldmatrix.trans)
#pragma unroll
        for (int kt = 0; kt < 4; kt++) {
#pragma unroll
            for (int ng = 0; ng < 4; ng++) {
                uint32_t vf[4];
                LDSM4T(vf, ub + (uint32_t)((64 + kt * 16 + vrow) * 72 + ng * 16 + vcof) * 2);
                MMAF16(acc_o[2 * ng],     pf[kt], vf[0], vf[1]);
                MMAF16(acc_o[2 * ng + 1], pf[kt], vf[2], vf[3]);
            }
        }
        __syncthreads();
    }

    // epilogue: normalize, write fp16 ctx
    const float inv0 = 1.f / l0, inv1 = 1.f / l1;
    const int r0 = b * LQ + q0 + wid * 16 + (lane >> 2);
    const int cbase = h * DH + (lane & 3) * 2;
#pragma unroll
    for (int nt = 0; nt < 8; nt++) {
        const int col = cbase + nt * 8;
        *(__half2*)&Ch[(size_t)r0 * EMBED + col] =
            __floats2half2_rn(acc_o[nt][0] * inv0, acc_o[nt][1] * inv0);
        *(__half2*)&Ch[(size_t)(r0 + 8) * EMBED + col] =
            __floats2half2_rn(acc_o[nt][2] * inv1, acc_o[nt][3] * inv1);
    }
}

// ---------------- residual + LayerNorm (in-place on out) ------------------------
__global__ __launch_bounds__(256) void resid_ln(
    float* __restrict__ out, const float* __restrict__ qseq,
    const float* __restrict__ gamma, const float* __restrict__ beta)
{
    const int row = blockIdx.x;
    const int tid = threadIdx.x;
    const size_t base = (size_t)row * EMBED + tid * 4;

    float4 o = *(float4*)&out[base];
    float4 q = *(const float4*)&qseq[base];
    float x0 = o.x + q.x, x1 = o.y + q.y, x2 = o.z + q.z, x3 = o.w + q.w;

    float s  = x0 + x1 + x2 + x3;
    float ss = fmaf(x0, x0, fmaf(x1, x1, fmaf(x2, x2, x3 * x3)));
#pragma unroll
    for (int off = 16; off >= 1; off >>= 1) {
        s  += __shfl_xor_sync(0xffffffffu, s, off);
        ss += __shfl_xor_sync(0xffffffffu, ss, off);
    }

    __shared__ float rs[8], rss[8];
    const int warp = tid >> 5, lane = tid & 31;
    if (lane == 0) { rs[warp] = s; rss[warp] = ss; }
    __syncthreads();
    if (tid == 0) {
        float S = 0.f, SS = 0.f;
#pragma unroll
        for (int w = 0; w < 8; w++) { S += rs[w]; SS += rss[w]; }
        rs[0] = S; rss[0] = SS;
    }
    __syncthreads();

    const float mean = rs[0] * (1.0f / EMBED);
    const float var  = rss[0] * (1.0f / EMBED) - mean * mean;
    const float r    = rsqrtf(var + 1e-5f);

    float4 g = *(const float4*)&gamma[tid * 4];
    float4 bt = *(const float4*)&beta[tid * 4];
    float4 y = make_float4((x0 - mean) * r * g.x + bt.x,
                           (x1 - mean) * r * g.y + bt.y,
                           (x2 - mean) * r * g.z + bt.z,
                           (x3 - mean) * r * g.w + bt.w);
    *(float4*)&out[base] = y;
}

// ---------------- launch ---------------------------------------------------------
extern "C" void kernel_launch(void* const* d_in, const int* in_sizes, int n_in,
                              void* d_out, int out_size)
{
    const float* qseq  = (const float*)d_in[0];
    const float* kvseq = (const float*)d_in[1];
    // d_in[2] = prompt_size (unused: reference applies no masking)
    const float* Wq = (const float*)d_in[3];
    const float* bq = (const float*)d_in[4];
    const float* Wk = (const float*)d_in[5];
    const float* bk = (const float*)d_in[6];
    const float* Wv = (const float*)d_in[7];
    const float* bv = (const float*)d_in[8];
    const float* Wo = (const float*)d_in[9];
    const float* bo = (const float*)d_in[10];
    const float* gamma = (const float*)d_in[11];
    const float* beta  = (const float*)d_in[12];
    float* out = (float*)d_out;

    __half *qh, *kh, *vh, *ch, *xq, *xkv, *wq, *wk, *wv, *wo;
    cudaGetSymbolAddress((void**)&qh, g_Qh);
    cudaGetSymbolAddress((void**)&kh, g_Kh);
    cudaGetSymbolAddress((void**)&vh, g_Vh);
    cudaGetSymbolAddress((void**)&ch, g_Ch);
    cudaGetSymbolAddress((void**)&xq, g_Xq);
    cudaGetSymbolAddress((void**)&xkv, g_Xkv);
    cudaGetSymbolAddress((void**)&wq, g_Wqh);
    cudaGetSymbolAddress((void**)&wk, g_Wkh);
    cudaGetSymbolAddress((void**)&wv, g_Wvh);
    cudaGetSymbolAddress((void**)&wo, g_Woh);

    const int totalConv = 2 * NA4 + 4 * NW4;   // 3145728
    conv_all<<<totalConv / 256, 256>>>(qseq, kvseq, Wq, Wk, Wv, Wo,
                                       xq, xkv, wq, wk, wv, wo);

    dim3 qkvgrid(EMBED / 128, MROWS / 128, 3);   // (8, 32, 3)
    gemm_qkv<<<qkvgrid, 256>>>(xq, xkv, wq, wk, wv, bq, bk, bv, qh, kh, vh);

    dim3 agrid(LQ / 128, HEADS, BATCH);          // (16, 16, 2)
    flash_attn_f16<<<agrid, 256>>>(qh, kh, vh, ch);

    dim3 ggrid(EMBED / 128, MROWS / 128);        // (8, 32)
    gemm_f16f<<<ggrid, 256>>>(ch, wo, bo, out);

    resid_ln<<<MROWS, 256>>>(out, qseq, gamma, beta);
}

// round 10
// speedup vs baseline: 7.8138x; 1.1753x over previous
#include <cuda_runtime.h>
#include <cuda_fp16.h>
#include <cstdint>
#include <math.h>

#define EMBED 1024
#define HEADS 16
#define DH 64
#define BATCH 2
#define LQ 2048
#define LK 2048
#define MROWS (BATCH * LQ)   // 4096

// ---------------- scratch (static device globals; no allocation) ----------------
__device__ __half g_Qh[(size_t)MROWS * EMBED];
__device__ __half g_Kh[(size_t)MROWS * EMBED];
__device__ __half g_Vh[(size_t)MROWS * EMBED];
__device__ __half g_Ch[(size_t)MROWS * EMBED];    // attention ctx
__device__ __half g_Xq[(size_t)MROWS * EMBED];    // qseq fp16
__device__ __half g_Xkv[(size_t)MROWS * EMBED];   // kvseq fp16
__device__ __half g_Wqh[(size_t)EMBED * EMBED];
__device__ __half g_Wkh[(size_t)EMBED * EMBED];
__device__ __half g_Wvh[(size_t)EMBED * EMBED];
__device__ __half g_Woh[(size_t)EMBED * EMBED];

// ---------------- PTX helpers (sm_80+ baseline features only) --------------------
__device__ __forceinline__ uint32_t smem_u32(const void* p) {
    uint32_t a;
    asm("{ .reg .u64 t; cvta.to.shared.u64 t, %1; cvt.u32.u64 %0, t; }" : "=r"(a) : "l"(p));
    return a;
}

#define LDSM4(r, addr) \
    asm volatile("ldmatrix.sync.aligned.m8n8.x4.shared.b16 {%0,%1,%2,%3}, [%4];" \
                 : "=r"((r)[0]), "=r"((r)[1]), "=r"((r)[2]), "=r"((r)[3]) : "r"(addr))

#define LDSM4T(r, addr) \
    asm volatile("ldmatrix.sync.aligned.m8n8.x4.trans.shared.b16 {%0,%1,%2,%3}, [%4];" \
                 : "=r"((r)[0]), "=r"((r)[1]), "=r"((r)[2]), "=r"((r)[3]) : "r"(addr))

#define MMAF16(d, a, b0, b1) \
    asm volatile("mma.sync.aligned.m16n8k16.row.col.f32.f16.f16.f32 " \
                 "{%0,%1,%2,%3}, {%4,%5,%6,%7}, {%8,%9}, {%0,%1,%2,%3};" \
                 : "+f"((d)[0]), "+f"((d)[1]), "+f"((d)[2]), "+f"((d)[3]) \
                 : "r"((a)[0]), "r"((a)[1]), "r"((a)[2]), "r"((a)[3]), "r"(b0), "r"(b1))

#define CP16(dst, src) \
    asm volatile("cp.async.cg.shared.global [%0], [%1], 16;" :: "r"(dst), "l"(src) : "memory")
#define CP_COMMIT() asm volatile("cp.async.commit_group;" ::: "memory")
#define CP_WAIT1()  asm volatile("cp.async.wait_group 1;" ::: "memory")
#define CP_WAIT0()  asm volatile("cp.async.wait_group 0;" ::: "memory")

__device__ __forceinline__ uint32_t pack_half2(float a, float b) {
    __half2 h = __floats2half2_rn(a, b);
    return *(uint32_t*)&h;
}

// exp(x) for x <= 0 on the fma/alu pipes (no MUFU). rel err ~2e-6.
__device__ __forceinline__ float fast_exp(float x) {
    x = fmaxf(x, -80.f);
    float t = x * 1.4426950408889634f;
    float r = t + 12582912.f;            // round to nearest int (2^23 * 1.5)
    float n = r - 12582912.f;
    float f = t - n;                      // f in [-0.5, 0.5]
    float p = 1.3333558146e-3f;
    p = fmaf(p, f, 9.6179630648e-3f);
    p = fmaf(p, f, 5.5504108664e-2f);
    p = fmaf(p, f, 2.4022650696e-1f);
    p = fmaf(p, f, 6.9314718056e-1f);
    p = fmaf(p, f, 1.0f);
    int e = __float_as_int(r) << 23;      // == n << 23 (mod 2^32)
    return __int_as_float(__float_as_int(p) + e);
}

// ---------------- fused fp32 -> fp16 convert (all 6 tensors, 1 launch) ----------
#define NA8 (MROWS * EMBED / 8)   // 524288
#define NW8 (EMBED * EMBED / 8)   // 131072

__global__ __launch_bounds__(256) void conv_all(
    const float* __restrict__ qseq, const float* __restrict__ kvseq,
    const float* __restrict__ Wq, const float* __restrict__ Wk,
    const float* __restrict__ Wv, const float* __restrict__ Wo,
    __half* __restrict__ xq, __half* __restrict__ xkv,
    __half* __restrict__ wq, __half* __restrict__ wk,
    __half* __restrict__ wv, __half* __restrict__ wo)
{
    int i = blockIdx.x * 256 + threadIdx.x;
    const float* src;
    __half* dst;
    int off;
    if (i < NA8)            { src = qseq;  dst = xq;  off = i; }
    else if (i < 2 * NA8)   { src = kvseq; dst = xkv; off = i - NA8; }
    else {
        int j = i - 2 * NA8;
        int w = j / NW8;
        off = j - w * NW8;
        src = (w == 0) ? Wq : (w == 1) ? Wk : (w == 2) ? Wv : Wo;
        dst = (w == 0) ? wq : (w == 1) ? wk : (w == 2) ? wv : wo;
    }
    float4 v0 = ((const float4*)src)[2 * off];
    float4 v1 = ((const float4*)src)[2 * off + 1];
    __half2* d = (__half2*)(dst + (size_t)off * 8);
    d[0] = __floats2half2_rn(v0.x, v0.y);
    d[1] = __floats2half2_rn(v0.z, v0.w);
    d[2] = __floats2half2_rn(v1.x, v1.y);
    d[3] = __floats2half2_rn(v1.z, v1.w);
}

// ---------------- fp16 HMMA GEMM, cp.async 2-stage pipeline ----------------------
// C[4096, 1024] = A @ B^T + bias; tile 128x128, BK=32.
#define SSTR 40
#define ABUF_B (128 * SSTR * 2)    // 10240 bytes per stage buffer

struct SmemF16 {
    __align__(16) __half A[2][128 * SSTR];
    __align__(16) __half B[2][128 * SSTR];
};

__device__ __forceinline__ void mainloop_f16(
    SmemF16& s, const __half* __restrict__ A, const __half* __restrict__ B,
    int bm, int bn, int wm, int wn, int lane, float acc[4][4][4])
{
    const int tid = threadIdx.x;
    const int r0g = tid >> 2;            // 0..63
    const int r1g = r0g + 64;            // 64..127
    const int k0g = (tid & 3) * 8;

    const int a_row = (lane & 15);
    const int a_kof = (lane >> 4) * 8;
    const int b_row = (lane & 7) + (lane >> 4) * 8;
    const int b_kof = ((lane >> 3) & 1) * 8;

    const uint32_t base = smem_u32(&s);
    const uint32_t aoff0 = (uint32_t)(r0g * SSTR + k0g) * 2;
    const uint32_t aoff1 = (uint32_t)(r1g * SSTR + k0g) * 2;

    const __half* gA = A + (size_t)(bm + r0g) * EMBED + k0g;
    const __half* gB = B + (size_t)(bn + r0g) * EMBED + k0g;

    // prologue: stage 0 into buffer 0
    CP16(base + aoff0, gA);
    CP16(base + aoff1, gA + 64 * EMBED);
    CP16(base + 2 * ABUF_B + aoff0, gB);
    CP16(base + 2 * ABUF_B + aoff1, gB + 64 * EMBED);
    CP_COMMIT();

    for (int kb = 0; kb < 32; kb++) {
        const int cur = kb & 1;
        if (kb < 31) {
            const int nb = cur ^ 1;
            const int kn = (kb + 1) * 32;
            CP16(base + nb * ABUF_B + aoff0, gA + kn);
            CP16(base + nb * ABUF_B + aoff1, gA + kn + 64 * EMBED);
            CP16(base + 2 * ABUF_B + nb * ABUF_B + aoff0, gB + kn);
            CP16(base + 2 * ABUF_B + nb * ABUF_B + aoff1, gB + kn + 64 * EMBED);
            CP_COMMIT();
            CP_WAIT1();
        } else {
            CP_WAIT0();
        }
        __syncthreads();

        const uint32_t uA = base + cur * ABUF_B;
        const uint32_t uB = base + 2 * ABUF_B + cur * ABUF_B;
#pragma unroll
        for (int ks = 0; ks < 2; ks++) {
            const int k0 = ks * 16;
            uint32_t fA[4][4], fB[2][4];
#pragma unroll
            for (int mt = 0; mt < 4; mt++) {
                uint32_t off = (uint32_t)((wm + mt * 16 + a_row) * SSTR + k0 + a_kof) * 2;
                LDSM4(fA[mt], uA + off);
            }
#pragma unroll
            for (int np = 0; np < 2; np++) {
                uint32_t off = (uint32_t)((wn + np * 16 + b_row) * SSTR + k0 + b_kof) * 2;
                LDSM4(fB[np], uB + off);
            }
#pragma unroll
            for (int mt = 0; mt < 4; mt++) {
#pragma unroll
                for (int nt = 0; nt < 4; nt++) {
                    const int np = nt >> 1, pr = (nt & 1) * 2;
                    MMAF16(acc[mt][nt], fA[mt], fB[np][pr], fB[np][pr + 1]);
                }
            }
        }
        __syncthreads();
    }
}

// Fused Q/K/V projections: grid.z selects which.
__global__ __launch_bounds__(256, 2) void gemm_qkv(
    const __half* __restrict__ xq, const __half* __restrict__ xkv,
    const __half* __restrict__ wq, const __half* __restrict__ wk,
    const __half* __restrict__ wv,
    const float* __restrict__ bq, const float* __restrict__ bk,
    const float* __restrict__ bv,
    __half* __restrict__ qh, __half* __restrict__ kh, __half* __restrict__ vh)
{
    __shared__ SmemF16 s;
    const int z = blockIdx.z;
    const __half* A = (z == 0) ? xq : xkv;
    const __half* B = (z == 0) ? wq : (z == 1) ? wk : wv;
    const float* bias = (z == 0) ? bq : (z == 1) ? bk : bv;
    __half* C = (z == 0) ? qh : (z == 1) ? kh : vh;
    const float scale = (z == 0) ? 0.125f : 1.0f;

    const int tid = threadIdx.x, wid = tid >> 5, lane = tid & 31;
    const int bm = blockIdx.y * 128, bn = blockIdx.x * 128;
    const int wm = (wid >> 2) * 64, wn = (wid & 3) * 32;

    float acc[4][4][4];
#pragma unroll
    for (int i = 0; i < 4; i++)
#pragma unroll
        for (int j = 0; j < 4; j++)
#pragma unroll
            for (int v = 0; v < 4; v++) acc[i][j][v] = 0.f;

    mainloop_f16(s, A, B, bm, bn, wm, wn, lane, acc);

    const int er = lane >> 2;
    const int ec = (lane & 3) * 2;
#pragma unroll
    for (int nt = 0; nt < 4; nt++) {
        const int gc = bn + wn + nt * 8 + ec;
        const float bx = bias[gc], by = bias[gc + 1];
#pragma unroll
        for (int mt = 0; mt < 4; mt++) {
            const int gr = bm + wm + mt * 16 + er;
            *(__half2*)&C[(size_t)gr * EMBED + gc] =
                __floats2half2_rn((acc[mt][nt][0] + bx) * scale,
                                  (acc[mt][nt][1] + by) * scale);
            *(__half2*)&C[(size_t)(gr + 8) * EMBED + gc] =
                __floats2half2_rn((acc[mt][nt][2] + bx) * scale,
                                  (acc[mt][nt][3] + by) * scale);
        }
    }
}

// fp32-output variant (O projection)
__global__ __launch_bounds__(256, 2) void gemm_f16f(
    const __half* __restrict__ A, const __half* __restrict__ B,
    const float* __restrict__ bias, float* __restrict__ C)
{
    __shared__ SmemF16 s;
    const int tid = threadIdx.x, wid = tid >> 5, lane = tid & 31;
    const int bm = blockIdx.y * 128, bn = blockIdx.x * 128;
    const int wm = (wid >> 2) * 64, wn = (wid & 3) * 32;

    float acc[4][4][4];
#pragma unroll
    for (int i = 0; i < 4; i++)
#pragma unroll
        for (int j = 0; j < 4; j++)
#pragma unroll
            for (int v = 0; v < 4; v++) acc[i][j][v] = 0.f;

    mainloop_f16(s, A, B, bm, bn, wm, wn, lane, acc);

    const int er = lane >> 2;
    const int ec = (lane & 3) * 2;
#pragma unroll
    for (int nt = 0; nt < 4; nt++) {
        const int gc = bn + wn + nt * 8 + ec;
        const float bx = bias[gc], by = bias[gc + 1];
#pragma unroll
        for (int mt = 0; mt < 4; mt++) {
            const int gr = bm + wm + mt * 16 + er;
            *(float2*)&C[(size_t)gr * EMBED + gc] =
                make_float2(acc[mt][nt][0] + bx, acc[mt][nt][1] + by);
            *(float2*)&C[(size_t)(gr + 8) * EMBED + gc] =
                make_float2(acc[mt][nt][2] + bx, acc[mt][nt][3] + by);
        }
    }
}

// ---------------- fp16 HMMA flash attention, cp.async 2-stage K/V ----------------
// CTA: 128 q-rows x (b,h). 8 warps, each owns 16 rows. 64-key tiles.
#define KVBUF_B (128 * 72 * 2)     // 18432 bytes per stage (K rows 0-63, V rows 64-127)

__global__ __launch_bounds__(256, 2) void flash_attn_f16(
    const __half* __restrict__ Qh, const __half* __restrict__ Kh,
    const __half* __restrict__ Vh, __half* __restrict__ Ch)
{
    __shared__ __align__(16) __half smKV[2][128 * 72];

    const int b = blockIdx.z, h = blockIdx.y;
    const int q0 = blockIdx.x * 128;
    const int tid = threadIdx.x, wid = tid >> 5, lane = tid & 31;

    // stage Q tile 128x64 into buffer 0, lift to fragments
    for (int u = tid; u < 1024; u += 256) {
        int r = u >> 3, c8 = (u & 7) * 8;
        *(uint4*)&smKV[0][r * 72 + c8] =
            *(const uint4*)(Qh + (size_t)(b * LQ + q0 + r) * EMBED + h * DH + c8);
    }
    __syncthreads();
    uint32_t qf[4][4];
    {
        const int arow = wid * 16 + (lane & 15);
        const int akof = (lane >> 4) * 8;
#pragma unroll
        for (int kt = 0; kt < 4; kt++)
            LDSM4(qf[kt], smem_u32(&smKV[0][arow * 72 + kt * 16 + akof]));
    }
    __syncthreads();

    const uint32_t kvbase = smem_u32(smKV);
    const int cr0 = tid >> 3;                 // 0..31
    const int cr1 = cr0 + 32;                 // 32..63
    const int cc8 = (tid & 7) * 8;

    // prologue: tile 0 into buffer 0
    {
        size_t g0 = (size_t)(b * LK + cr0) * EMBED + h * DH + cc8;
        size_t g1 = (size_t)(b * LK + cr1) * EMBED + h * DH + cc8;
        CP16(kvbase + (uint32_t)(cr0 * 72 + cc8) * 2, Kh + g0);
        CP16(kvbase + (uint32_t)((64 + cr0) * 72 + cc8) * 2, Vh + g0);
        CP16(kvbase + (uint32_t)(cr1 * 72 + cc8) * 2, Kh + g1);
        CP16(kvbase + (uint32_t)((64 + cr1) * 72 + cc8) * 2, Vh + g1);
        CP_COMMIT();
    }

    float acc_o[8][4];
#pragma unroll
    for (int i = 0; i < 8; i++)
#pragma unroll
        for (int j = 0; j < 4; j++) acc_o[i][j] = 0.f;
    float m0 = -1e30f, m1 = -1e30f, l0 = 0.f, l1 = 0.f;

    const int brow = (lane & 7) + ((lane >> 4) << 3);
    const int bkof = ((lane >> 3) & 1) << 3;
    const int vrow = lane & 15;
    const int vcof = (lane >> 4) << 3;

    for (int t = 0; t < LK / 64; t++) {
        const int cur = t & 1;
        if (t < LK / 64 - 1) {
            const int nb = cur ^ 1;
            const int k0n = (t + 1) * 64;
            size_t g0 = (size_t)(b * LK + k0n + cr0) * EMBED + h * DH + cc8;
            size_t g1 = (size_t)(b * LK + k0n + cr1) * EMBED + h * DH + cc8;
            CP16(kvbase + nb * KVBUF_B + (uint32_t)(cr0 * 72 + cc8) * 2, Kh + g0);
            CP16(kvbase + nb * KVBUF_B + (uint32_t)((64 + cr0) * 72 + cc8) * 2, Vh + g0);
            CP16(kvbase + nb * KVBUF_B + (uint32_t)(cr1 * 72 + cc8) * 2, Kh + g1);
            CP16(kvbase + nb * KVBUF_B + (uint32_t)((64 + cr1) * 72 + cc8) * 2, Vh + g1);
            CP_COMMIT();
            CP_WAIT1();
        } else {
            CP_WAIT0();
        }
        __syncthreads();
        const uint32_t ub = kvbase + cur * KVBUF_B;

        // S = Q @ K^T  (fp16, fp32 acc)
        float s[8][4];
#pragma unroll
        for (int i = 0; i < 8; i++)
#pragma unroll
            for (int j = 0; j < 4; j++) s[i][j] = 0.f;
#pragma unroll
        for (int kt = 0; kt < 4; kt++) {
#pragma unroll
            for (int np = 0; np < 4; np++) {
                uint32_t kf[4];
                LDSM4(kf, ub + (uint32_t)((np * 16 + brow) * 72 + kt * 16 + bkof) * 2);
                MMAF16(s[2 * np],     qf[kt], kf[0], kf[1]);
                MMAF16(s[2 * np + 1], qf[kt], kf[2], kf[3]);
            }
        }

        // online softmax (rows lane/4 and lane/4+8 of this warp's 16)
        float mx0 = -1e30f, mx1 = -1e30f;
#pragma unroll
        for (int nt = 0; nt < 8; nt++) {
            mx0 = fmaxf(mx0, fmaxf(s[nt][0], s[nt][1]));
            mx1 = fmaxf(mx1, fmaxf(s[nt][2], s[nt][3]));
        }
        mx0 = fmaxf(mx0, __shfl_xor_sync(0xffffffffu, mx0, 1));
        mx0 = fmaxf(mx0, __shfl_xor_sync(0xffffffffu, mx0, 2));
        mx1 = fmaxf(mx1, __shfl_xor_sync(0xffffffffu, mx1, 1));
        mx1 = fmaxf(mx1, __shfl_xor_sync(0xffffffffu, mx1, 2));
        float mn0 = fmaxf(m0, mx0), mn1 = fmaxf(m1, mx1);
        float c0 = fast_exp(m0 - mn0), c1 = fast_exp(m1 - mn1);
        m0 = mn0; m1 = mn1;
        float s0 = 0.f, s1 = 0.f;
#pragma unroll
        for (int nt = 0; nt < 8; nt++) {
            s[nt][0] = fast_exp(s[nt][0] - m0);
            s[nt][1] = fast_exp(s[nt][1] - m0);
            s[nt][2] = fast_exp(s[nt][2] - m1);
            s[nt][3] = fast_exp(s[nt][3] - m1);
            s0 += s[nt][0] + s[nt][1];
            s1 += s[nt][2] + s[nt][3];
        }
        s0 += __shfl_xor_sync(0xffffffffu, s0, 1);
        s0 += __shfl_xor_sync(0xffffffffu, s0, 2);
        s1 += __shfl_xor_sync(0xffffffffu, s1, 1);
        s1 += __shfl_xor_sync(0xffffffffu, s1, 2);
        l0 = l0 * c0 + s0;
        l1 = l1 * c1 + s1;
#pragma unroll
        for (int nt = 0; nt < 8; nt++) {
            acc_o[nt][0] *= c0; acc_o[nt][1] *= c0;
            acc_o[nt][2] *= c1; acc_o[nt][3] *= c1;
        }

        // P fragments (C-frag -> A-frag identity)
        uint32_t pf[4][4];
#pragma unroll
        for (int kt = 0; kt < 4; kt++) {
            pf[kt][0] = pack_half2(s[2 * kt][0],     s[2 * kt][1]);
            pf[kt][1] = pack_half2(s[2 * kt][2],     s[2 * kt][3]);
            pf[kt][2] = pack_half2(s[2 * kt + 1][0], s[2 * kt + 1][1]);
            pf[kt][3] = pack_half2(s[2 * kt + 1][2], s[2 * kt + 1][3]);
        }

        // O += P @ V  (V via ldmatrix.trans)
#pragma unroll
        for (int kt = 0; kt < 4; kt++) {
#pragma unroll
            for (int ng = 0; ng < 4; ng++) {
                uint32_t vf[4];
                LDSM4T(vf, ub + (uint32_t)((64 + kt * 16 + vrow) * 72 + ng * 16 + vcof) * 2);
                MMAF16(acc_o[2 * ng],     pf[kt], vf[0], vf[1]);
                MMAF16(acc_o[2 * ng + 1], pf[kt], vf[2], vf[3]);
            }
        }
        __syncthreads();
    }

    // epilogue: normalize, write fp16 ctx
    const float inv0 = 1.f / l0, inv1 = 1.f / l1;
    const int r0 = b * LQ + q0 + wid * 16 + (lane >> 2);
    const int cbase = h * DH + (lane & 3) * 2;
#pragma unroll
    for (int nt = 0; nt < 8; nt++) {
        const int col = cbase + nt * 8;
        *(__half2*)&Ch[(size_t)r0 * EMBED + col] =
            __floats2half2_rn(acc_o[nt][0] * inv0, acc_o[nt][1] * inv0);
        *(__half2*)&Ch[(size_t)(r0 + 8) * EMBED + col] =
            __floats2half2_rn(acc_o[nt][2] * inv1, acc_o[nt][3] * inv1);
    }
}

// ---------------- residual + LayerNorm (in-place on out) ------------------------
__global__ __launch_bounds__(256) void resid_ln(
    float* __restrict__ out, const float* __restrict__ qseq,
    const float* __restrict__ gamma, const float* __restrict__ beta)
{
    const int row = blockIdx.x;
    const int tid = threadIdx.x;
    const size_t base = (size_t)row * EMBED + tid * 4;

    float4 o = *(float4*)&out[base];
    float4 q = *(const float4*)&qseq[base];
    float x0 = o.x + q.x, x1 = o.y + q.y, x2 = o.z + q.z, x3 = o.w + q.w;

    float s  = x0 + x1 + x2 + x3;
    float ss = fmaf(x0, x0, fmaf(x1, x1, fmaf(x2, x2, x3 * x3)));
#pragma unroll
    for (int off = 16; off >= 1; off >>= 1) {
        s  += __shfl_xor_sync(0xffffffffu, s, off);
        ss += __shfl_xor_sync(0xffffffffu, ss, off);
    }

    __shared__ float rs[8], rss[8];
    const int warp = tid >> 5, lane = tid & 31;
    if (lane == 0) { rs[warp] = s; rss[warp] = ss; }
    __syncthreads();
    if (tid == 0) {
        float S = 0.f, SS = 0.f;
#pragma unroll
        for (int w = 0; w < 8; w++) { S += rs[w]; SS += rss[w]; }
        rs[0] = S; rss[0] = SS;
    }
    __syncthreads();

    const float mean = rs[0] * (1.0f / EMBED);
    const float var  = rss[0] * (1.0f / EMBED) - mean * mean;
    const float r    = rsqrtf(var + 1e-5f);

    float4 g = *(const float4*)&gamma[tid * 4];
    float4 bt = *(const float4*)&beta[tid * 4];
    float4 y = make_float4((x0 - mean) * r * g.x + bt.x,
                           (x1 - mean) * r * g.y + bt.y,
                           (x2 - mean) * r * g.z + bt.z,
                           (x3 - mean) * r * g.w + bt.w);
    *(float4*)&out[base] = y;
}

// ---------------- launch ---------------------------------------------------------
extern "C" void kernel_launch(void* const* d_in, const int* in_sizes, int n_in,
                              void* d_out, int out_size)
{
    const float* qseq  = (const float*)d_in[0];
    const float* kvseq = (const float*)d_in[1];
    // d_in[2] = prompt_size (unused: reference applies no masking)
    const float* Wq = (const float*)d_in[3];
    const float* bq = (const float*)d_in[4];
    const float* Wk = (const float*)d_in[5];
    const float* bk = (const float*)d_in[6];
    const float* Wv = (const float*)d_in[7];
    const float* bv = (const float*)d_in[8];
    const float* Wo = (const float*)d_in[9];
    const float* bo = (const float*)d_in[10];
    const float* gamma = (const float*)d_in[11];
    const float* beta  = (const float*)d_in[12];
    float* out = (float*)d_out;

    __half *qh, *kh, *vh, *ch, *xq, *xkv, *wq, *wk, *wv, *wo;
    cudaGetSymbolAddress((void**)&qh, g_Qh);
    cudaGetSymbolAddress((void**)&kh, g_Kh);
    cudaGetSymbolAddress((void**)&vh, g_Vh);
    cudaGetSymbolAddress((void**)&ch, g_Ch);
    cudaGetSymbolAddress((void**)&xq, g_Xq);
    cudaGetSymbolAddress((void**)&xkv, g_Xkv);
    cudaGetSymbolAddress((void**)&wq, g_Wqh);
    cudaGetSymbolAddress((void**)&wk, g_Wkh);
    cudaGetSymbolAddress((void**)&wv, g_Wvh);
    cudaGetSymbolAddress((void**)&wo, g_Woh);

    const int totalConv = 2 * NA8 + 4 * NW8;   // 1572864
    conv_all<<<totalConv / 256, 256>>>(qseq, kvseq, Wq, Wk, Wv, Wo,
                                       xq, xkv, wq, wk, wv, wo);

    dim3 qkvgrid(EMBED / 128, MROWS / 128, 3);   // (8, 32, 3)
    gemm_qkv<<<qkvgrid, 256>>>(xq, xkv, wq, wk, wv, bq, bk, bv, qh, kh, vh);

    dim3 agrid(LQ / 128, HEADS, BATCH);          // (16, 16, 2)
    flash_attn_f16<<<agrid, 256>>>(qh, kh, vh, ch);

    dim3 ggrid(EMBED / 128, MROWS / 128);        // (8, 32)
    gemm_f16f<<<ggrid, 256>>>(ch, wo, bo, out);

    resid_ln<<<MROWS, 256>>>(out, qseq, gamma, beta);
}

// round 12
// speedup vs baseline: 8.3715x; 1.0714x over previous
#include <cuda_runtime.h>
#include <cuda_fp16.h>
#include <cstdint>
#include <math.h>

#define EMBED 1024
#define HEADS 16
#define DH 64
#define BATCH 2
#define LQ 2048
#define LK 2048
#define MROWS (BATCH * LQ)   // 4096

// ---------------- scratch (static device globals; no allocation) ----------------
__device__ __half g_Qh[(size_t)MROWS * EMBED];
__device__ __half g_Kh[(size_t)MROWS * EMBED];
__device__ __half g_Vh[(size_t)MROWS * EMBED];
__device__ __half g_Ch[(size_t)MROWS * EMBED];    // attention ctx
__device__ __half g_Xq[(size_t)MROWS * EMBED];    // qseq fp16
__device__ __half g_Xkv[(size_t)MROWS * EMBED];   // kvseq fp16
__device__ __half g_Wqh[(size_t)EMBED * EMBED];
__device__ __half g_Wkh[(size_t)EMBED * EMBED];
__device__ __half g_Wvh[(size_t)EMBED * EMBED];
__device__ __half g_Woh[(size_t)EMBED * EMBED];

// ---------------- PTX helpers (sm_80+ baseline features only) --------------------
__device__ __forceinline__ uint32_t smem_u32(const void* p) {
    uint32_t a;
    asm("{ .reg .u64 t; cvta.to.shared.u64 t, %1; cvt.u32.u64 %0, t; }" : "=r"(a) : "l"(p));
    return a;
}

#define LDSM4(r, addr) \
    asm volatile("ldmatrix.sync.aligned.m8n8.x4.shared.b16 {%0,%1,%2,%3}, [%4];" \
                 : "=r"((r)[0]), "=r"((r)[1]), "=r"((r)[2]), "=r"((r)[3]) : "r"(addr))

#define LDSM4T(r, addr) \
    asm volatile("ldmatrix.sync.aligned.m8n8.x4.trans.shared.b16 {%0,%1,%2,%3}, [%4];" \
                 : "=r"((r)[0]), "=r"((r)[1]), "=r"((r)[2]), "=r"((r)[3]) : "r"(addr))

#define MMAF16(d, a, b0, b1) \
    asm volatile("mma.sync.aligned.m16n8k16.row.col.f32.f16.f16.f32 " \
                 "{%0,%1,%2,%3}, {%4,%5,%6,%7}, {%8,%9}, {%0,%1,%2,%3};" \
                 : "+f"((d)[0]), "+f"((d)[1]), "+f"((d)[2]), "+f"((d)[3]) \
                 : "r"((a)[0]), "r"((a)[1]), "r"((a)[2]), "r"((a)[3]), "r"(b0), "r"(b1))

#define CP16(dst, src) \
    asm volatile("cp.async.cg.shared.global [%0], [%1], 16;" :: "r"(dst), "l"(src) : "memory")
#define CP_COMMIT() asm volatile("cp.async.commit_group;" ::: "memory")
#define CP_WAIT0()  asm volatile("cp.async.wait_group 0;" ::: "memory")

__device__ __forceinline__ uint32_t pack_half2(float a, float b) {
    __half2 h = __floats2half2_rn(a, b);
    return *(uint32_t*)&h;
}

// exp(x) for x <= 0 on the fma/alu pipes (no MUFU). rel err ~2e-6.
__device__ __forceinline__ float fast_exp(float x) {
    x = fmaxf(x, -80.f);
    float t = x * 1.4426950408889634f;
    float r = t + 12582912.f;            // round to nearest int (2^23 * 1.5)
    float n = r - 12582912.f;
    float f = t - n;                      // f in [-0.5, 0.5]
    float p = 1.3333558146e-3f;
    p = fmaf(p, f, 9.6179630648e-3f);
    p = fmaf(p, f, 5.5504108664e-2f);
    p = fmaf(p, f, 2.4022650696e-1f);
    p = fmaf(p, f, 6.9314718056e-1f);
    p = fmaf(p, f, 1.0f);
    int e = __float_as_int(r) << 23;      // == n << 23 (mod 2^32)
    return __int_as_float(__float_as_int(p) + e);
}

// ---------------- fused fp32 -> fp16 convert (all 6 tensors, 1 launch) ----------
#define NA8 (MROWS * EMBED / 8)   // 524288
#define NW8 (EMBED * EMBED / 8)   // 131072

__global__ __launch_bounds__(256) void conv_all(
    const float* __restrict__ qseq, const float* __restrict__ kvseq,
    const float* __restrict__ Wq, const float* __restrict__ Wk,
    const float* __restrict__ Wv, const float* __restrict__ Wo,
    __half* __restrict__ xq, __half* __restrict__ xkv,
    __half* __restrict__ wq, __half* __restrict__ wk,
    __half* __restrict__ wv, __half* __restrict__ wo)
{
    int i = blockIdx.x * 256 + threadIdx.x;
    const float* src;
    __half* dst;
    int off;
    if (i < NA8)            { src = qseq;  dst = xq;  off = i; }
    else if (i < 2 * NA8)   { src = kvseq; dst = xkv; off = i - NA8; }
    else {
        int j = i - 2 * NA8;
        int w = j / NW8;
        off = j - w * NW8;
        src = (w == 0) ? Wq : (w == 1) ? Wk : (w == 2) ? Wv : Wo;
        dst = (w == 0) ? wq : (w == 1) ? wk : (w == 2) ? wv : wo;
    }
    float4 v0 = ((const float4*)src)[2 * off];
    float4 v1 = ((const float4*)src)[2 * off + 1];
    __half2* d = (__half2*)(dst + (size_t)off * 8);
    d[0] = __floats2half2_rn(v0.x, v0.y);
    d[1] = __floats2half2_rn(v0.z, v0.w);
    d[2] = __floats2half2_rn(v1.x, v1.y);
    d[3] = __floats2half2_rn(v1.z, v1.w);
}

// ---------------- fp16 HMMA GEMM, cp.async 2-stage, 1 barrier/stage ---------------
// C[4096, 1024] = A @ B^T + bias; tile 128x128, BK=32.
#define SSTR 40
#define ABUF_B (128 * SSTR * 2)    // 10240 bytes per stage buffer

struct SmemF16 {
    __align__(16) __half A[2][128 * SSTR];
    __align__(16) __half B[2][128 * SSTR];
};

__device__ __forceinline__ void mainloop_f16(
    SmemF16& s, const __half* __restrict__ A, const __half* __restrict__ B,
    int bm, int bn, int wm, int wn, int lane, float acc[4][4][4])
{
    const int tid = threadIdx.x;
    const int r0g = tid >> 2;            // 0..63
    const int r1g = r0g + 64;            // 64..127
    const int k0g = (tid & 3) * 8;

    const int a_row = (lane & 15);
    const int a_kof = (lane >> 4) * 8;
    const int b_row = (lane & 7) + (lane >> 4) * 8;
    const int b_kof = ((lane >> 3) & 1) * 8;

    const uint32_t base = smem_u32(&s);
    const uint32_t aoff0 = (uint32_t)(r0g * SSTR + k0g) * 2;
    const uint32_t aoff1 = (uint32_t)(r1g * SSTR + k0g) * 2;

    const __half* gA = A + (size_t)(bm + r0g) * EMBED + k0g;
    const __half* gB = B + (size_t)(bn + r0g) * EMBED + k0g;

    // prologue: stage 0 into buffer 0
    CP16(base + aoff0, gA);
    CP16(base + aoff1, gA + 64 * EMBED);
    CP16(base + 2 * ABUF_B + aoff0, gB);
    CP16(base + 2 * ABUF_B + aoff1, gB + 64 * EMBED);
    CP_COMMIT();

    for (int kb = 0; kb < 32; kb++) {
        const int cur = kb & 1;
        // data for 'cur' ready + all warps done reading the buffer we're about to fill
        CP_WAIT0();
        __syncthreads();

        if (kb < 31) {
            const int nb = cur ^ 1;
            const int kn = (kb + 1) * 32;
            CP16(base + nb * ABUF_B + aoff0, gA + kn);
            CP16(base + nb * ABUF_B + aoff1, gA + kn + 64 * EMBED);
            CP16(base + 2 * ABUF_B + nb * ABUF_B + aoff0, gB + kn);
            CP16(base + 2 * ABUF_B + nb * ABUF_B + aoff1, gB + kn + 64 * EMBED);
            CP_COMMIT();
        }

        const uint32_t uA = base + cur * ABUF_B;
        const uint32_t uB = base + 2 * ABUF_B + cur * ABUF_B;
#pragma unroll
        for (int ks = 0; ks < 2; ks++) {
            const int k0 = ks * 16;
            uint32_t fA[4][4], fB[2][4];
#pragma unroll
            for (int mt = 0; mt < 4; mt++) {
                uint32_t off = (uint32_t)((wm + mt * 16 + a_row) * SSTR + k0 + a_kof) * 2;
                LDSM4(fA[mt], uA + off);
            }
#pragma unroll
            for (int np = 0; np < 2; np++) {
                uint32_t off = (uint32_t)((wn + np * 16 + b_row) * SSTR + k0 + b_kof) * 2;
                LDSM4(fB[np], uB + off);
            }
#pragma unroll
            for (int mt = 0; mt < 4; mt++) {
#pragma unroll
                for (int nt = 0; nt < 4; nt++) {
                    const int np = nt >> 1, pr = (nt & 1) * 2;
                    MMAF16(acc[mt][nt], fA[mt], fB[np][pr], fB[np][pr + 1]);
                }
            }
        }
        // no trailing barrier: next iteration's top barrier covers the WAR hazard
    }
}

// Fused Q/K/V projections: grid.z selects which.
__global__ __launch_bounds__(256, 2) void gemm_qkv(
    const __half* __restrict__ xq, const __half* __restrict__ xkv,
    const __half* __restrict__ wq, const __half* __restrict__ wk,
    const __half* __restrict__ wv,
    const float* __restrict__ bq, const float* __restrict__ bk,
    const float* __restrict__ bv,
    __half* __restrict__ qh, __half* __restrict__ kh, __half* __restrict__ vh)
{
    __shared__ SmemF16 s;
    const int z = blockIdx.z;
    const __half* A = (z == 0) ? xq : xkv;
    const __half* B = (z == 0) ? wq : (z == 1) ? wk : wv;
    const float* bias = (z == 0) ? bq : (z == 1) ? bk : bv;
    __half* C = (z == 0) ? qh : (z == 1) ? kh : vh;
    const float scale = (z == 0) ? 0.125f : 1.0f;

    const int tid = threadIdx.x, wid = tid >> 5, lane = tid & 31;
    const int bm = blockIdx.y * 128, bn = blockIdx.x * 128;
    const int wm = (wid >> 2) * 64, wn = (wid & 3) * 32;

    float acc[4][4][4];
#pragma unroll
    for (int i = 0; i < 4; i++)
#pragma unroll
        for (int j = 0; j < 4; j++)
#pragma unroll
            for (int v = 0; v < 4; v++) acc[i][j][v] = 0.f;

    mainloop_f16(s, A, B, bm, bn, wm, wn, lane, acc);

    const int er = lane >> 2;
    const int ec = (lane & 3) * 2;
#pragma unroll
    for (int nt = 0; nt < 4; nt++) {
        const int gc = bn + wn + nt * 8 + ec;
        const float bx = bias[gc], by = bias[gc + 1];
#pragma unroll
        for (int mt = 0; mt < 4; mt++) {
            const int gr = bm + wm + mt * 16 + er;
            *(__half2*)&C[(size_t)gr * EMBED + gc] =
                __floats2half2_rn((acc[mt][nt][0] + bx) * scale,
                                  (acc[mt][nt][1] + by) * scale);
            *(__half2*)&C[(size_t)(gr + 8) * EMBED + gc] =
                __floats2half2_rn((acc[mt][nt][2] + bx) * scale,
                                  (acc[mt][nt][3] + by) * scale);
        }
    }
}

// fp32-output variant (O projection)
__global__ __launch_bounds__(256, 2) void gemm_f16f(
    const __half* __restrict__ A, const __half* __restrict__ B,
    const float* __restrict__ bias, float* __restrict__ C)
{
    __shared__ SmemF16 s;
    const int tid = threadIdx.x, wid = tid >> 5, lane = tid & 31;
    const int bm = blockIdx.y * 128, bn = blockIdx.x * 128;
    const int wm = (wid >> 2) * 64, wn = (wid & 3) * 32;

    float acc[4][4][4];
#pragma unroll
    for (int i = 0; i < 4; i++)
#pragma unroll
        for (int j = 0; j < 4; j++)
#pragma unroll
            for (int v = 0; v < 4; v++) acc[i][j][v] = 0.f;

    mainloop_f16(s, A, B, bm, bn, wm, wn, lane, acc);

    const int er = lane >> 2;
    const int ec = (lane & 3) * 2;
#pragma unroll
    for (int nt = 0; nt < 4; nt++) {
        const int gc = bn + wn + nt * 8 + ec;
        const float bx = bias[gc], by = bias[gc + 1];
#pragma unroll
        for (int mt = 0; mt < 4; mt++) {
            const int gr = bm + wm + mt * 16 + er;
            *(float2*)&C[(size_t)gr * EMBED + gc] =
                make_float2(acc[mt][nt][0] + bx, acc[mt][nt][1] + by);
            *(float2*)&C[(size_t)(gr + 8) * EMBED + gc] =
                make_float2(acc[mt][nt][2] + bx, acc[mt][nt][3] + by);
        }
    }
}

// ---------------- fp16 HMMA flash attention, 2-stage K/V, 1 barrier/tile ---------
// CTA: 128 q-rows x (b,h). 8 warps, each owns 16 rows. 64-key tiles.
#define KVBUF_B (128 * 72 * 2)     // 18432 bytes per stage (K rows 0-63, V rows 64-127)

__global__ __launch_bounds__(256, 2) void flash_attn_f16(
    const __half* __restrict__ Qh, const __half* __restrict__ Kh,
    const __half* __restrict__ Vh, __half* __restrict__ Ch)
{
    __shared__ __align__(16) __half smKV[2][128 * 72];

    const int b = blockIdx.z, h = blockIdx.y;
    const int q0 = blockIdx.x * 128;
    const int tid = threadIdx.x, wid = tid >> 5, lane = tid & 31;

    // stage Q tile 128x64 into buffer 0, lift to fragments
    for (int u = tid; u < 1024; u += 256) {
        int r = u >> 3, c8 = (u & 7) * 8;
        *(uint4*)&smKV[0][r * 72 + c8] =
            *(const uint4*)(Qh + (size_t)(b * LQ + q0 + r) * EMBED + h * DH + c8);
    }
    __syncthreads();
    uint32_t qf[4][4];
    {
        const int arow = wid * 16 + (lane & 15);
        const int akof = (lane >> 4) * 8;
#pragma unroll
        for (int kt = 0; kt < 4; kt++)
            LDSM4(qf[kt], smem_u32(&smKV[0][arow * 72 + kt * 16 + akof]));
    }
    __syncthreads();   // everyone done reading Q from buffer 0

    const uint32_t kvbase = smem_u32(smKV);
    const int cr0 = tid >> 3;                 // 0..31
    const int cr1 = cr0 + 32;                 // 32..63
    const int cc8 = (tid & 7) * 8;

    // prologue: tile 0 into buffer 0
    {
        size_t g0 = (size_t)(b * LK + cr0) * EMBED + h * DH + cc8;
        size_t g1 = (size_t)(b * LK + cr1) * EMBED + h * DH + cc8;
        CP16(kvbase + (uint32_t)(cr0 * 72 + cc8) * 2, Kh + g0);
        CP16(kvbase + (uint32_t)((64 + cr0) * 72 + cc8) * 2, Vh + g0);
        CP16(kvbase + (uint32_t)(cr1 * 72 + cc8) * 2, Kh + g1);
        CP16(kvbase + (uint32_t)((64 + cr1) * 72 + cc8) * 2, Vh + g1);
        CP_COMMIT();
    }

    float acc_o[8][4];
#pragma unroll
    for (int i = 0; i < 8; i++)
#pragma unroll
        for (int j = 0; j < 4; j++) acc_o[i][j] = 0.f;
    float m0 = -1e30f, m1 = -1e30f, l0 = 0.f, l1 = 0.f;

    const int brow = (lane & 7) + ((lane >> 4) << 3);
    const int bkof = ((lane >> 3) & 1) << 3;
    const int vrow = lane & 15;
    const int vcof = (lane >> 4) << 3;

    for (int t = 0; t < LK / 64; t++) {
        const int cur = t & 1;
        CP_WAIT0();
        __syncthreads();

        if (t < LK / 64 - 1) {
            const int nb = cur ^ 1;
            const int k0n = (t + 1) * 64;
            size_t g0 = (size_t)(b * LK + k0n + cr0) * EMBED + h * DH + cc8;
            size_t g1 = (size_t)(b * LK + k0n + cr1) * EMBED + h * DH + cc8;
            CP16(kvbase + nb * KVBUF_B + (uint32_t)(cr0 * 72 + cc8) * 2, Kh + g0);
            CP16(kvbase + nb * KVBUF_B + (uint32_t)((64 + cr0) * 72 + cc8) * 2, Vh + g0);
            CP16(kvbase + nb * KVBUF_B + (uint32_t)(cr1 * 72 + cc8) * 2, Kh + g1);
            CP16(kvbase + nb * KVBUF_B + (uint32_t)((64 + cr1) * 72 + cc8) * 2, Vh + g1);
            CP_COMMIT();
        }
        const uint32_t ub = kvbase + cur * KVBUF_B;

        // S = Q @ K^T  (fp16, fp32 acc)
        float s[8][4];
#pragma unroll
        for (int i = 0; i < 8; i++)
#pragma unroll
            for (int j = 0; j < 4; j++) s[i][j] = 0.f;
#pragma unroll
        for (int kt = 0; kt < 4; kt++) {
#pragma unroll
            for (int np = 0; np < 4; np++) {
                uint32_t kf[4];
                LDSM4(kf, ub + (uint32_t)((np * 16 + brow) * 72 + kt * 16 + bkof) * 2);
                MMAF16(s[2 * np],     qf[kt], kf[0], kf[1]);
                MMAF16(s[2 * np + 1], qf[kt], kf[2], kf[3]);
            }
        }

        // online softmax (rows lane/4 and lane/4+8 of this warp's 16)
        float mx0 = -1e30f, mx1 = -1e30f;
#pragma unroll
        for (int nt = 0; nt < 8; nt++) {
            mx0 = fmaxf(mx0, fmaxf(s[nt][0], s[nt][1]));
            mx1 = fmaxf(mx1, fmaxf(s[nt][2], s[nt][3]));
        }
        mx0 = fmaxf(mx0, __shfl_xor_sync(0xffffffffu, mx0, 1));
        mx0 = fmaxf(mx0, __shfl_xor_sync(0xffffffffu, mx0, 2));
        mx1 = fmaxf(mx1, __shfl_xor_sync(0xffffffffu, mx1, 1));
        mx1 = fmaxf(mx1, __shfl_xor_sync(0xffffffffu, mx1, 2));
        float mn0 = fmaxf(m0, mx0), mn1 = fmaxf(m1, mx1);
        float c0 = fast_exp(m0 - mn0), c1 = fast_exp(m1 - mn1);
        m0 = mn0; m1 = mn1;
        float s0 = 0.f, s1 = 0.f;
#pragma unroll
        for (int nt = 0; nt < 8; nt++) {
            s[nt][0] = fast_exp(s[nt][0] - m0);
            s[nt][1] = fast_exp(s[nt][1] - m0);
            s[nt][2] = fast_exp(s[nt][2] - m1);
            s[nt][3] = fast_exp(s[nt][3] - m1);
            s0 += s[nt][0] + s[nt][1];
            s1 += s[nt][2] + s[nt][3];
        }
        s0 += __shfl_xor_sync(0xffffffffu, s0, 1);
        s0 += __shfl_xor_sync(0xffffffffu, s0, 2);
        s1 += __shfl_xor_sync(0xffffffffu, s1, 1);
        s1 += __shfl_xor_sync(0xffffffffu, s1, 2);
        l0 = l0 * c0 + s0;
        l1 = l1 * c1 + s1;
#pragma unroll
        for (int nt = 0; nt < 8; nt++) {
            acc_o[nt][0] *= c0; acc_o[nt][1] *= c0;
            acc_o[nt][2] *= c1; acc_o[nt][3] *= c1;
        }

        // P fragments (C-frag -> A-frag identity)
        uint32_t pf[4][4];
#pragma unroll
        for (int kt = 0; kt < 4; kt++) {
            pf[kt][0] = pack_half2(s[2 * kt][0],     s[2 * kt][1]);
            pf[kt][1] = pack_half2(s[2 * kt][2],     s[2 * kt][3]);
            pf[kt][2] = pack_half2(s[2 * kt + 1][0], s[2 * kt + 1][1]);
            pf[kt][3] = pack_half2(s[2 * kt + 1][2], s[2 * kt + 1][3]);
        }

        // O += P @ V  (V via ldmatrix.trans)
#pragma unroll
        for (int kt = 0; kt < 4; kt++) {
#pragma unroll
            for (int ng = 0; ng < 4; ng++) {
                uint32_t vf[4];
                LDSM4T(vf, ub + (uint32_t)((64 + kt * 16 + vrow) * 72 + ng * 16 + vcof) * 2);
                MMAF16(acc_o[2 * ng],     pf[kt], vf[0], vf[1]);
                MMAF16(acc_o[2 * ng + 1], pf[kt], vf[2], vf[3]);
            }
        }
        // no trailing barrier: next iteration's top barrier covers the WAR hazard
    }

    // epilogue: normalize, write fp16 ctx
    const float inv0 = 1.f / l0, inv1 = 1.f / l1;
    const int r0 = b * LQ + q0 + wid * 16 + (lane >> 2);
    const int cbase = h * DH + (lane & 3) * 2;
#pragma unroll
    for (int nt = 0; nt < 8; nt++) {
        const int col = cbase + nt * 8;
        *(__half2*)&Ch[(size_t)r0 * EMBED + col] =
            __floats2half2_rn(acc_o[nt][0] * inv0, acc_o[nt][1] * inv0);
        *(__half2*)&Ch[(size_t)(r0 + 8) * EMBED + col] =
            __floats2half2_rn(acc_o[nt][2] * inv1, acc_o[nt][3] * inv1);
    }
}

// ---------------- residual + LayerNorm (in-place on out) ------------------------
__global__ __launch_bounds__(256) void resid_ln(
    float* __restrict__ out, const float* __restrict__ qseq,
    const float* __restrict__ gamma, const float* __restrict__ beta)
{
    const int row = blockIdx.x;
    const int tid = threadIdx.x;
    const size_t base = (size_t)row * EMBED + tid * 4;

    float4 o = *(float4*)&out[base];
    float4 q = *(const float4*)&qseq[base];
    float x0 = o.x + q.x, x1 = o.y + q.y, x2 = o.z + q.z, x3 = o.w + q.w;

    float s  = x0 + x1 + x2 + x3;
    float ss = fmaf(x0, x0, fmaf(x1, x1, fmaf(x2, x2, x3 * x3)));
#pragma unroll
    for (int off = 16; off >= 1; off >>= 1) {
        s  += __shfl_xor_sync(0xffffffffu, s, off);
        ss += __shfl_xor_sync(0xffffffffu, ss, off);
    }

    __shared__ float rs[8], rss[8];
    const int warp = tid >> 5, lane = tid & 31;
    if (lane == 0) { rs[warp] = s; rss[warp] = ss; }
    __syncthreads();
    if (tid == 0) {
        float S = 0.f, SS = 0.f;
#pragma unroll
        for (int w = 0; w < 8; w++) { S += rs[w]; SS += rss[w]; }
        rs[0] = S; rss[0] = SS;
    }
    __syncthreads();

    const float mean = rs[0] * (1.0f / EMBED);
    const float var  = rss[0] * (1.0f / EMBED) - mean * mean;
    const float r    = rsqrtf(var + 1e-5f);

    float4 g = *(const float4*)&gamma[tid * 4];
    float4 bt = *(const float4*)&beta[tid * 4];
    float4 y = make_float4((x0 - mean) * r * g.x + bt.x,
                           (x1 - mean) * r * g.y + bt.y,
                           (x2 - mean) * r * g.z + bt.z,
                           (x3 - mean) * r * g.w + bt.w);
    *(float4*)&out[base] = y;
}

// ---------------- launch ---------------------------------------------------------
extern "C" void kernel_launch(void* const* d_in, const int* in_sizes, int n_in,
                              void* d_out, int out_size)
{
    const float* qseq  = (const float*)d_in[0];
    const float* kvseq = (const float*)d_in[1];
    // d_in[2] = prompt_size (unused: reference applies no masking)
    const float* Wq = (const float*)d_in[3];
    const float* bq = (const float*)d_in[4];
    const float* Wk = (const float*)d_in[5];
    const float* bk = (const float*)d_in[6];
    const float* Wv = (const float*)d_in[7];
    const float* bv = (const float*)d_in[8];
    const float* Wo = (const float*)d_in[9];
    const float* bo = (const float*)d_in[10];
    const float* gamma = (const float*)d_in[11];
    const float* beta  = (const float*)d_in[12];
    float* out = (float*)d_out;

    __half *qh, *kh, *vh, *ch, *xq, *xkv, *wq, *wk, *wv, *wo;
    cudaGetSymbolAddress((void**)&qh, g_Qh);
    cudaGetSymbolAddress((void**)&kh, g_Kh);
    cudaGetSymbolAddress((void**)&vh, g_Vh);
    cudaGetSymbolAddress((void**)&ch, g_Ch);
    cudaGetSymbolAddress((void**)&xq, g_Xq);
    cudaGetSymbolAddress((void**)&xkv, g_Xkv);
    cudaGetSymbolAddress((void**)&wq, g_Wqh);
    cudaGetSymbolAddress((void**)&wk, g_Wkh);
    cudaGetSymbolAddress((void**)&wv, g_Wvh);
    cudaGetSymbolAddress((void**)&wo, g_Woh);

    const int totalConv = 2 * NA8 + 4 * NW8;   // 1572864
    conv_all<<<totalConv / 256, 256>>>(qseq, kvseq, Wq, Wk, Wv, Wo,
                                       xq, xkv, wq, wk, wv, wo);

    dim3 qkvgrid(EMBED / 128, MROWS / 128, 3);   // (8, 32, 3)
    gemm_qkv<<<qkvgrid, 256>>>(xq, xkv, wq, wk, wv, bq, bk, bv, qh, kh, vh);

    dim3 agrid(LQ / 128, HEADS, BATCH);          // (16, 16, 2)
    flash_attn_f16<<<agrid, 256>>>(qh, kh, vh, ch);

    dim3 ggrid(EMBED / 128, MROWS / 128);        // (8, 32)
    gemm_f16f<<<ggrid, 256>>>(ch, wo, bo, out);

    resid_ln<<<MROWS, 256>>>(out, qseq, gamma, beta);
}